// round 12
// baseline (speedup 1.0000x reference)
#include <cuda_runtime.h>
#include <cstdint>

// Problem constants
#define BB   128      // batch
#define LL   200      // seq len
#define NC   10000    // num classes
#define DD   128      // feature dim
#define MM   64       // memory slots
#define GG   4        // m-groups in scan
#define MG   (MM/GG)  // 16 m per group
#define NOUT 512      // padded rows of Wbig (449 real)

// Wbig row layout:
//  [0,64)    Mk          -> w logits
//  [64,192)  e_W         -> e linear
//  [192,320) a_W         -> a linear
//  [320,448) f_W[:,128:] -> fk (k-half of f)
//  [448]     df_W        -> que_diff linear
//  [449,512) zero pad

__device__ float g_Wbig[NOUT * DD];          // 256 KB
__device__ float g_Z[NC * NOUT];             // 20.5 MB  per-class table
__device__ float g_fWT[DD * DD];             // f_W[:, :128] transposed: [i][j]
__device__ float g_ebias[2 * DD];            // e_W @ v_emb[r] + e_b
__device__ float g_abias[2 * DD];            // a_W @ v_emb[r] + a_b
__device__ float g_preads[BB * LL * GG * DD];// 52 MB partial reads

// ---------------------------------------------------------------------------
// K0: build Wbig, fW-transpose, r-dependent biases
// ---------------------------------------------------------------------------
__global__ void k0_prep(const float* __restrict__ Mk,
                        const float* __restrict__ eW,
                        const float* __restrict__ aW,
                        const float* __restrict__ fW,
                        const float* __restrict__ dfW,
                        const float* __restrict__ vemb,
                        const float* __restrict__ eb,
                        const float* __restrict__ ab) {
    int tid = threadIdx.x; // 256 threads
    for (int idx = tid; idx < NOUT * DD; idx += 256) {
        int n = idx >> 7, i = idx & 127;
        float v;
        if (n < 64)        v = Mk[n * DD + i];
        else if (n < 192)  v = eW[(n - 64) * DD + i];
        else if (n < 320)  v = aW[(n - 192) * DD + i];
        else if (n < 448)  v = fW[(n - 320) * (2 * DD) + DD + i];
        else if (n == 448) v = dfW[i];
        else               v = 0.f;
        g_Wbig[idx] = v;
    }
    for (int idx = tid; idx < DD * DD; idx += 256) {
        int i = idx >> 7, j = idx & 127;
        g_fWT[i * DD + j] = fW[j * (2 * DD) + i];
    }
    // biases: tid = r*128 + d  (exactly 256)
    {
        int r = tid >> 7, d = tid & 127;
        float acc_e = 0.f, acc_a = 0.f;
        for (int i = 0; i < DD; i++) {
            float vv = vemb[r * DD + i];
            acc_e = fmaf(eW[d * DD + i], vv, acc_e);
            acc_a = fmaf(aW[d * DD + i], vv, acc_a);
        }
        g_ebias[tid] = acc_e + eb[d];
        g_abias[tid] = acc_a + ab[d];
    }
}

// ---------------------------------------------------------------------------
// K1: Z[c][n] = k_emb[c,:] . Wbig[n,:]   (10000 x 512 x 128 GEMM)
// Tile 128x128, BK=32, 256 threads, 8x8 microtile. Both smem tiles in [k][col]
// layout so fragment loads are float4 / conflict-free.
// ---------------------------------------------------------------------------
__global__ void __launch_bounds__(256) k1_gemm(const float* __restrict__ kemb) {
    __shared__ __align__(16) float As[32 * 128];
    __shared__ __align__(16) float Bs[32 * 128];
    const int cb = blockIdx.x * 128;
    const int nb = blockIdx.y * 128;
    const int tid = threadIdx.x;
    const int tx = tid & 15, ty = tid >> 4;
    const int m0 = ty * 8, n0 = tx * 8;

    float acc[8][8];
#pragma unroll
    for (int i = 0; i < 8; i++)
#pragma unroll
        for (int j = 0; j < 8; j++) acc[i][j] = 0.f;

    for (int ko = 0; ko < DD; ko += 32) {
        // A tile: 128 classes x 32 k
#pragma unroll
        for (int it = 0; it < 4; it++) {
            int idx = tid + it * 256;           // float4 units, 0..1023
            int kq = idx & 7, mm = idx >> 3;
            int c = cb + mm;
            int cc = c < NC ? c : NC - 1;
            float4 v = *(const float4*)&kemb[cc * DD + ko + kq * 4];
            if (c >= NC) v = make_float4(0.f, 0.f, 0.f, 0.f);
            As[(kq * 4 + 0) * 128 + mm] = v.x;
            As[(kq * 4 + 1) * 128 + mm] = v.y;
            As[(kq * 4 + 2) * 128 + mm] = v.z;
            As[(kq * 4 + 3) * 128 + mm] = v.w;
        }
        // B tile: 128 out-rows x 32 k
#pragma unroll
        for (int it = 0; it < 4; it++) {
            int idx = tid + it * 256;
            int kq = idx & 7, nn = idx >> 3;
            float4 v = *(const float4*)&g_Wbig[(nb + nn) * DD + ko + kq * 4];
            Bs[(kq * 4 + 0) * 128 + nn] = v.x;
            Bs[(kq * 4 + 1) * 128 + nn] = v.y;
            Bs[(kq * 4 + 2) * 128 + nn] = v.z;
            Bs[(kq * 4 + 3) * 128 + nn] = v.w;
        }
        __syncthreads();
#pragma unroll
        for (int k = 0; k < 32; k++) {
            float a[8], b[8];
            *(float4*)&a[0] = *(const float4*)&As[k * 128 + m0];
            *(float4*)&a[4] = *(const float4*)&As[k * 128 + m0 + 4];
            *(float4*)&b[0] = *(const float4*)&Bs[k * 128 + n0];
            *(float4*)&b[4] = *(const float4*)&Bs[k * 128 + n0 + 4];
#pragma unroll
            for (int i = 0; i < 8; i++)
#pragma unroll
                for (int j = 0; j < 8; j++)
                    acc[i][j] = fmaf(a[i], b[j], acc[i][j]);
        }
        __syncthreads();
    }
#pragma unroll
    for (int i = 0; i < 8; i++) {
        int c = cb + m0 + i;
        if (c < NC) {
            *(float4*)&g_Z[c * NOUT + nb + n0]     = *(float4*)&acc[i][0];
            *(float4*)&g_Z[c * NOUT + nb + n0 + 4] = *(float4*)&acc[i][4];
        }
    }
}

// ---------------------------------------------------------------------------
// K2: per class: softmax over Z[c][0:64], add f_b to fk region, tanh qd.
// One warp per class.
// ---------------------------------------------------------------------------
__global__ void k2_post(const float* __restrict__ f_b,
                        const float* __restrict__ df_b) {
    int c = blockIdx.x * 4 + (threadIdx.x >> 5);
    int lane = threadIdx.x & 31;
    float* z = &g_Z[c * NOUT];
    float x0 = z[lane], x1 = z[lane + 32];
    float mx = fmaxf(x0, x1);
#pragma unroll
    for (int off = 16; off; off >>= 1)
        mx = fmaxf(mx, __shfl_xor_sync(0xffffffffu, mx, off));
    float e0 = __expf(x0 - mx), e1 = __expf(x1 - mx);
    float s = e0 + e1;
#pragma unroll
    for (int off = 16; off; off >>= 1)
        s += __shfl_xor_sync(0xffffffffu, s, off);
    float inv = 1.f / s;
    z[lane] = e0 * inv;
    z[lane + 32] = e1 * inv;
#pragma unroll
    for (int i = 0; i < 4; i++)
        z[320 + lane + i * 32] += f_b[lane + i * 32];
    if (lane == 0) z[448] = tanhf(z[448] + df_b[0]);
}

// ---------------------------------------------------------------------------
// K3: sequential scan. Block = (batch b, m-group g). Thread d owns column d,
// MG=16 state rows in registers. Partial reads -> g_preads. Prefetch t+1
// table rows; one barrier per step (w double-buffer in smem).
// ---------------------------------------------------------------------------
__global__ void __launch_bounds__(128) k3_scan(const int* __restrict__ q,
                                               const int* __restrict__ r,
                                               const float* __restrict__ Mv0) {
    __shared__ int qs[LL];
    __shared__ int rs[LL];
    __shared__ float ws[2][MG];
    const int b = blockIdx.x >> 2;
    const int g = blockIdx.x & 3;
    const int d = threadIdx.x;

    for (int i = d; i < LL; i += 128) {
        qs[i] = q[b * LL + i];
        rs[i] = r[b * LL + i];
    }
    float Mv[MG];
#pragma unroll
    for (int j = 0; j < MG; j++) Mv[j] = Mv0[(g * MG + j) * DD + d];
    const float eb0 = g_ebias[d],      eb1 = g_ebias[DD + d];
    const float ab0 = g_abias[d],      ab1 = g_abias[DD + d];
    __syncthreads();

    int c0 = qs[0];
    if (d < MG) ws[0][d] = g_Z[c0 * NOUT + g * MG + d];
    float eln = g_Z[c0 * NOUT + 64 + d];
    float aln = g_Z[c0 * NOUT + 192 + d];
    int rcur = rs[0];
    __syncthreads();

    float* outp = &g_preads[(b * LL * GG + g) * DD + d];

    for (int t = 0; t < LL; t++) {
        const int tn = (t < LL - 1) ? t + 1 : LL - 1;
        const int cn = qs[tn];
        // prefetch next step
        float eln_n = g_Z[cn * NOUT + 64 + d];
        float aln_n = g_Z[cn * NOUT + 192 + d];
        float w_n = 0.f;
        if (d < MG) w_n = g_Z[cn * NOUT + g * MG + d];
        const int rn = rs[tn];

        // nonlinearities for current step
        const float ee = 1.f / (1.f + __expf(-(eln + (rcur ? eb1 : eb0))));
        const float aa = tanhf(aln + (rcur ? ab1 : ab0));

        float r0 = 0.f, r1 = 0.f;
        const int buf = t & 1;
#pragma unroll
        for (int j = 0; j < MG; j += 2) {
            float w0 = ws[buf][j], w1 = ws[buf][j + 1];
            r0 = fmaf(w0, Mv[j], r0);
            r1 = fmaf(w1, Mv[j + 1], r1);
            Mv[j]     = fmaf(w0, fmaf(-ee, Mv[j],     aa), Mv[j]);
            Mv[j + 1] = fmaf(w1, fmaf(-ee, Mv[j + 1], aa), Mv[j + 1]);
        }
        outp[t * (GG * DD)] = r0 + r1;

        if (d < MG) ws[buf ^ 1][d] = w_n;
        eln = eln_n; aln = aln_n; rcur = rn;
        __syncthreads();
    }
}

// ---------------------------------------------------------------------------
// K4: epilogue. Block = 32 tokens, 128 threads (thread = output j).
// fWr column held in 128 registers per thread; reads staged in smem.
// ---------------------------------------------------------------------------
__global__ void __launch_bounds__(128) k4_final(const int* __restrict__ q,
                                                const float* __restrict__ abW,
                                                const float* __restrict__ ab_b,
                                                float* __restrict__ out) {
    __shared__ __align__(16) float rbuf[DD];
    __shared__ float fsum[4];
    const int tid = threadIdx.x;

    float wreg[DD];
#pragma unroll
    for (int i = 0; i < DD; i++) wreg[i] = g_fWT[i * DD + tid];
    const float myab = abW[tid];
    const float abb = ab_b[0];
    const int tok0 = blockIdx.x * 32;

    for (int tt = 0; tt < 32; tt++) {
        const int tok = tok0 + tt;
        const float* pr = &g_preads[tok * (GG * DD)];
        float rsum = pr[tid] + pr[DD + tid] + pr[2 * DD + tid] + pr[3 * DD + tid];
        __syncthreads();            // previous iter's rbuf/fsum readers done
        rbuf[tid] = rsum;
        __syncthreads();

        float a0 = 0.f, a1 = 0.f, a2 = 0.f, a3 = 0.f;
        const float4* rb4 = (const float4*)rbuf;
#pragma unroll
        for (int i4 = 0; i4 < 32; i4++) {
            float4 v = rb4[i4];
            a0 = fmaf(v.x, wreg[i4 * 4 + 0], a0);
            a1 = fmaf(v.y, wreg[i4 * 4 + 1], a1);
            a2 = fmaf(v.z, wreg[i4 * 4 + 2], a2);
            a3 = fmaf(v.w, wreg[i4 * 4 + 3], a3);
        }
        const int c = q[tok];
        const float fk = g_Z[c * NOUT + 320 + tid];
        const float f = tanhf(a0 + a1 + a2 + a3 + fk);
        float prod = f * myab;
#pragma unroll
        for (int off = 16; off; off >>= 1)
            prod += __shfl_xor_sync(0xffffffffu, prod, off);
        if ((tid & 31) == 0) fsum[tid >> 5] = prod;
        __syncthreads();
        if (tid == 0) {
            float s = fsum[0] + fsum[1] + fsum[2] + fsum[3];
            float stu = tanhf(s + abb);
            float qd = g_Z[c * NOUT + 448];
            float x = 3.f * stu - qd;
            out[tok] = 1.f / (1.f + __expf(-x));
        }
    }
}

// ---------------------------------------------------------------------------
extern "C" void kernel_launch(void* const* d_in, const int* in_sizes, int n_in,
                              void* d_out, int out_size) {
    const int*   q     = (const int*)d_in[0];
    const int*   r     = (const int*)d_in[1];
    const float* k_emb = (const float*)d_in[2];
    const float* v_emb = (const float*)d_in[3];
    const float* Mk    = (const float*)d_in[4];
    const float* Mv0   = (const float*)d_in[5];
    const float* f_W   = (const float*)d_in[6];
    const float* f_b   = (const float*)d_in[7];
    const float* e_W   = (const float*)d_in[8];
    const float* e_b   = (const float*)d_in[9];
    const float* a_W   = (const float*)d_in[10];
    const float* a_b   = (const float*)d_in[11];
    const float* ab_W  = (const float*)d_in[12];
    const float* ab_b  = (const float*)d_in[13];
    const float* df_W  = (const float*)d_in[14];
    const float* df_b  = (const float*)d_in[15];
    float* out = (float*)d_out;

    k0_prep<<<1, 256>>>(Mk, e_W, a_W, f_W, df_W, v_emb, e_b, a_b);
    dim3 g1((NC + 127) / 128, NOUT / 128);
    k1_gemm<<<g1, 256>>>(k_emb);
    k2_post<<<NC / 4, 128>>>(f_b, df_b);
    k3_scan<<<BB * GG, 128>>>(q, r, Mv0);
    k4_final<<<(BB * LL) / 32, 128>>>(q, ab_W, ab_b, out);
}

// round 13
// speedup vs baseline: 1.4940x; 1.4940x over previous
#include <cuda_runtime.h>
#include <cstdint>

// Problem constants
#define BB   128      // batch
#define LL   200      // seq len
#define NC   10000    // num classes
#define DD   128      // feature dim
#define MM   64       // memory slots
#define GG   4        // m-groups in scan
#define MG   (MM/GG)  // 16 m per group
#define NOUT 512      // padded rows of Wbig (449 real)
#define KT   10112    // padded class count (79*128) for kembT columns

// WbigT column layout (n index):
//  [0,64)    Mk          -> w logits
//  [64,192)  e_W         -> e linear
//  [192,320) a_W         -> a linear
//  [320,448) f_W[:,128:] -> fk (k-half of f)
//  [448]     df_W        -> que_diff linear
//  [449,512) zero pad

__device__ float g_WbigT[DD * NOUT];         // 256 KB, [i][n]
__device__ float g_kembT[DD * KT];           // 5.2 MB, [i][c]
__device__ float g_Z[NC * NOUT];             // 20.5 MB per-class table
__device__ float g_fWT[DD * DD];             // f_W[:, :128] transposed: [i][j]
__device__ float g_ebias[2 * DD];
__device__ float g_abias[2 * DD];
__device__ float g_preads[BB * LL * GG * DD];// 52 MB partial reads

// --------------------------- fast math helpers ----------------------------
__device__ __forceinline__ float fsigmoid(float x) {
    return __fdividef(1.f, 1.f + __expf(-x));
}
__device__ __forceinline__ float ftanh(float x) {
    // robust at +-inf: 1 - 2/(e^{2x}+1)
    return 1.f - __fdividef(2.f, __expf(2.f * x) + 1.f);
}
__device__ __forceinline__ uint32_t smem_u32(const void* p) {
    uint32_t r;
    asm("{ .reg .u64 t; cvta.to.shared.u64 t, %1; cvt.u32.u64 %0, t; }"
        : "=r"(r) : "l"(p));
    return r;
}
__device__ __forceinline__ void cp16(uint32_t s, const void* g) {
    asm volatile("cp.async.cg.shared.global [%0], [%1], 16;" :: "r"(s), "l"(g));
}

// ---------------------------------------------------------------------------
// K0: build WbigT, fW-transpose, r-dependent biases
// ---------------------------------------------------------------------------
__global__ void k0_prep(const float* __restrict__ Mk,
                        const float* __restrict__ eW,
                        const float* __restrict__ aW,
                        const float* __restrict__ fW,
                        const float* __restrict__ dfW,
                        const float* __restrict__ vemb,
                        const float* __restrict__ eb,
                        const float* __restrict__ ab) {
    int tid = threadIdx.x; // 256 threads
    for (int idx = tid; idx < NOUT * DD; idx += 256) {
        int n = idx & 511, i = idx >> 9;
        float v;
        if (n < 64)        v = Mk[n * DD + i];
        else if (n < 192)  v = eW[(n - 64) * DD + i];
        else if (n < 320)  v = aW[(n - 192) * DD + i];
        else if (n < 448)  v = fW[(n - 320) * (2 * DD) + DD + i];
        else if (n == 448) v = dfW[i];
        else               v = 0.f;
        g_WbigT[i * NOUT + n] = v;
    }
    for (int idx = tid; idx < DD * DD; idx += 256) {
        int i = idx >> 7, j = idx & 127;
        g_fWT[i * DD + j] = fW[j * (2 * DD) + i];
    }
    {   // biases: tid = r*128 + d  (exactly 256)
        int r = tid >> 7, d = tid & 127;
        float acc_e = 0.f, acc_a = 0.f;
        for (int i = 0; i < DD; i++) {
            float vv = vemb[r * DD + i];
            acc_e = fmaf(eW[d * DD + i], vv, acc_e);
            acc_a = fmaf(aW[d * DD + i], vv, acc_a);
        }
        g_ebias[tid] = acc_e + eb[d];
        g_abias[tid] = acc_a + ab[d];
    }
}

// ---------------------------------------------------------------------------
// K0t: transpose k_emb [NC,DD] -> g_kembT [DD,KT]
// ---------------------------------------------------------------------------
__global__ void k0_transpose(const float* __restrict__ kemb) {
    __shared__ float t[32][33];
    const int bx = blockIdx.x * 32;  // class dim
    const int by = blockIdx.y * 32;  // d dim
    const int x = threadIdx.x, y = threadIdx.y;
#pragma unroll
    for (int i = 0; i < 32; i += 8) {
        int c = bx + y + i;
        t[y + i][x] = (c < NC) ? kemb[c * DD + by + x] : 0.f;
    }
    __syncthreads();
#pragma unroll
    for (int i = 0; i < 32; i += 8) {
        g_kembT[(by + y + i) * KT + bx + x] = t[x][y + i];
    }
}

// ---------------------------------------------------------------------------
// K1: Z[c][n] = k_emb[c,:] . Wbig[n,:]   (10112 x 512 x 128 GEMM)
// cp.async double-buffered; operands pre-transposed so smem is [k][col].
// 128x128 tile, BK=32, 256 threads, 8x8 microtile.
// ---------------------------------------------------------------------------
__global__ void __launch_bounds__(256) k1_gemm() {
    __shared__ __align__(16) float As[2][32 * 128];
    __shared__ __align__(16) float Bs[2][32 * 128];
    const int cb = blockIdx.x * 128;
    const int nb = blockIdx.y * 128;
    const int tid = threadIdx.x;
    const int tx = tid & 15, ty = tid >> 4;
    const int m0 = ty * 8, n0 = tx * 8;

    float acc[8][8];
#pragma unroll
    for (int i = 0; i < 8; i++)
#pragma unroll
        for (int j = 0; j < 8; j++) acc[i][j] = 0.f;

    auto issue = [&](int buf, int ko) {
#pragma unroll
        for (int i = 0; i < 4; i++) {
            int f = tid + i * 256;            // float4 index, 0..1023
            int k = f >> 5, c4 = (f & 31) * 4;
            cp16(smem_u32(&As[buf][k * 128 + c4]),
                 &g_kembT[(ko + k) * KT + cb + c4]);
            cp16(smem_u32(&Bs[buf][k * 128 + c4]),
                 &g_WbigT[(ko + k) * NOUT + nb + c4]);
        }
        asm volatile("cp.async.commit_group;" ::: "memory");
    };

    issue(0, 0);
    for (int it = 0; it < 4; it++) {
        asm volatile("cp.async.wait_group 0;" ::: "memory");
        __syncthreads();
        if (it < 3) issue((it + 1) & 1, (it + 1) * 32);
        const float* Ab = &As[it & 1][0];
        const float* Bb = &Bs[it & 1][0];
#pragma unroll
        for (int k = 0; k < 32; k++) {
            float a[8], b[8];
            *(float4*)&a[0] = *(const float4*)&Ab[k * 128 + m0];
            *(float4*)&a[4] = *(const float4*)&Ab[k * 128 + m0 + 4];
            *(float4*)&b[0] = *(const float4*)&Bb[k * 128 + n0];
            *(float4*)&b[4] = *(const float4*)&Bb[k * 128 + n0 + 4];
#pragma unroll
            for (int i = 0; i < 8; i++)
#pragma unroll
                for (int j = 0; j < 8; j++)
                    acc[i][j] = fmaf(a[i], b[j], acc[i][j]);
        }
        __syncthreads();
    }
#pragma unroll
    for (int i = 0; i < 8; i++) {
        int c = cb + m0 + i;
        if (c < NC) {
            *(float4*)&g_Z[c * NOUT + nb + n0]     = *(float4*)&acc[i][0];
            *(float4*)&g_Z[c * NOUT + nb + n0 + 4] = *(float4*)&acc[i][4];
        }
    }
}

// ---------------------------------------------------------------------------
// K2: per class: softmax over Z[c][0:64], add f_b to fk region, tanh qd.
// One warp per class.
// ---------------------------------------------------------------------------
__global__ void k2_post(const float* __restrict__ f_b,
                        const float* __restrict__ df_b) {
    int c = blockIdx.x * 4 + (threadIdx.x >> 5);
    int lane = threadIdx.x & 31;
    float* z = &g_Z[c * NOUT];
    float x0 = z[lane], x1 = z[lane + 32];
    float mx = fmaxf(x0, x1);
#pragma unroll
    for (int off = 16; off; off >>= 1)
        mx = fmaxf(mx, __shfl_xor_sync(0xffffffffu, mx, off));
    float e0 = __expf(x0 - mx), e1 = __expf(x1 - mx);
    float s = e0 + e1;
#pragma unroll
    for (int off = 16; off; off >>= 1)
        s += __shfl_xor_sync(0xffffffffu, s, off);
    float inv = __fdividef(1.f, s);
    z[lane] = e0 * inv;
    z[lane + 32] = e1 * inv;
#pragma unroll
    for (int i = 0; i < 4; i++)
        z[320 + lane + i * 32] += f_b[lane + i * 32];
    if (lane == 0) z[448] = ftanh(z[448] + df_b[0]);
}

// ---------------------------------------------------------------------------
// K3: sequential scan. Block = (batch b, m-group g). Thread d owns column d,
// MG=16 state rows in registers. Entire w table (200x16) staged in smem up
// front -> ZERO barriers in the main loop. e/a rows prefetched 1 step ahead.
// ---------------------------------------------------------------------------
__global__ void __launch_bounds__(128) k3_scan(const int* __restrict__ q,
                                               const int* __restrict__ r,
                                               const float* __restrict__ Mv0) {
    __shared__ int qs[LL];
    __shared__ int rs[LL];
    __shared__ float wtab[LL * MG];   // 12.8 KB
    const int b = blockIdx.x >> 2;
    const int g = blockIdx.x & 3;
    const int d = threadIdx.x;

    for (int i = d; i < LL; i += 128) {
        qs[i] = q[b * LL + i];
        rs[i] = r[b * LL + i];
    }
    __syncthreads();
    for (int idx = d; idx < LL * MG; idx += 128)
        wtab[idx] = g_Z[qs[idx >> 4] * NOUT + g * MG + (idx & 15)];

    float Mv[MG];
#pragma unroll
    for (int j = 0; j < MG; j++) Mv[j] = Mv0[(g * MG + j) * DD + d];
    const float eb0 = g_ebias[d],      eb1 = g_ebias[DD + d];
    const float ab0 = g_abias[d],      ab1 = g_abias[DD + d];
    __syncthreads();

    float eln = g_Z[qs[0] * NOUT + 64 + d];
    float aln = g_Z[qs[0] * NOUT + 192 + d];
    int rcur = rs[0];

    float* outp = &g_preads[(b * LL * GG + g) * DD + d];

#pragma unroll 2
    for (int t = 0; t < LL; t++) {
        const int tn = (t < LL - 1) ? t + 1 : LL - 1;
        const int cn = qs[tn];
        // prefetch next step (hits L2-resident g_Z)
        float eln_n = g_Z[cn * NOUT + 64 + d];
        float aln_n = g_Z[cn * NOUT + 192 + d];
        const int rn = rs[tn];

        const float ee = fsigmoid(eln + (rcur ? eb1 : eb0));
        const float aa = ftanh(aln + (rcur ? ab1 : ab0));

        float r0 = 0.f, r1 = 0.f;
        const float* wp = &wtab[t * MG];
#pragma unroll
        for (int j = 0; j < MG; j += 2) {
            float w0 = wp[j], w1 = wp[j + 1];    // broadcast LDS
            r0 = fmaf(w0, Mv[j], r0);
            r1 = fmaf(w1, Mv[j + 1], r1);
            Mv[j]     = fmaf(w0, fmaf(-ee, Mv[j],     aa), Mv[j]);
            Mv[j + 1] = fmaf(w1, fmaf(-ee, Mv[j + 1], aa), Mv[j + 1]);
        }
        outp[t * (GG * DD)] = r0 + r1;

        eln = eln_n; aln = aln_n; rcur = rn;
    }
}

// ---------------------------------------------------------------------------
// K4: epilogue. Block = 64 tokens, 128 threads (thread = output j).
// fWr column held in 128 registers; 8 tokens staged per barrier batch.
// ---------------------------------------------------------------------------
__global__ void __launch_bounds__(128) k4_final(const int* __restrict__ q,
                                                const float* __restrict__ abW,
                                                const float* __restrict__ ab_b,
                                                float* __restrict__ out) {
    __shared__ __align__(16) float rbuf[8][DD];
    __shared__ float fsum[8][4];
    const int tid = threadIdx.x;
    const int warp = tid >> 5, lane = tid & 31;

    float wreg[DD];
#pragma unroll
    for (int i = 0; i < DD; i++) wreg[i] = g_fWT[i * DD + tid];
    const float myab = abW[tid];
    const float abb = ab_b[0];
    const int tok0 = blockIdx.x * 64;

    for (int tb = 0; tb < 64; tb += 8) {
        __syncthreads();   // rbuf/fsum reuse fence
#pragma unroll
        for (int k = 0; k < 8; k++) {
            int idx = tid + k * 128;           // 0..1023
            int tt = idx >> 7, dd = idx & 127;
            const float* pr = &g_preads[(tok0 + tb + tt) * (GG * DD)];
            rbuf[tt][dd] = pr[dd] + pr[DD + dd] + pr[2 * DD + dd] + pr[3 * DD + dd];
        }
        __syncthreads();

#pragma unroll 1
        for (int tt = 0; tt < 8; tt++) {
            float a0 = 0.f, a1 = 0.f, a2 = 0.f, a3 = 0.f;
            const float4* rb4 = (const float4*)rbuf[tt];
#pragma unroll
            for (int i4 = 0; i4 < 32; i4++) {
                float4 v = rb4[i4];
                a0 = fmaf(v.x, wreg[i4 * 4 + 0], a0);
                a1 = fmaf(v.y, wreg[i4 * 4 + 1], a1);
                a2 = fmaf(v.z, wreg[i4 * 4 + 2], a2);
                a3 = fmaf(v.w, wreg[i4 * 4 + 3], a3);
            }
            const int c = q[tok0 + tb + tt];    // uniform -> broadcast load
            const float fk = g_Z[c * NOUT + 320 + tid];
            const float f = ftanh(a0 + a1 + a2 + a3 + fk);
            float prod = f * myab;
#pragma unroll
            for (int off = 16; off; off >>= 1)
                prod += __shfl_xor_sync(0xffffffffu, prod, off);
            if (lane == 0) fsum[tt][warp] = prod;
        }
        __syncthreads();
        if (tid < 8) {
            const int tok = tok0 + tb + tid;
            const int c = q[tok];
            float s = fsum[tid][0] + fsum[tid][1] + fsum[tid][2] + fsum[tid][3];
            float stu = ftanh(s + abb);
            float qd = g_Z[c * NOUT + 448];
            out[tok] = fsigmoid(3.f * stu - qd);
        }
    }
}

// ---------------------------------------------------------------------------
extern "C" void kernel_launch(void* const* d_in, const int* in_sizes, int n_in,
                              void* d_out, int out_size) {
    const int*   q     = (const int*)d_in[0];
    const int*   r     = (const int*)d_in[1];
    const float* k_emb = (const float*)d_in[2];
    const float* v_emb = (const float*)d_in[3];
    const float* Mk    = (const float*)d_in[4];
    const float* Mv0   = (const float*)d_in[5];
    const float* f_W   = (const float*)d_in[6];
    const float* f_b   = (const float*)d_in[7];
    const float* e_W   = (const float*)d_in[8];
    const float* e_b   = (const float*)d_in[9];
    const float* a_W   = (const float*)d_in[10];
    const float* a_b   = (const float*)d_in[11];
    const float* ab_W  = (const float*)d_in[12];
    const float* ab_b  = (const float*)d_in[13];
    const float* df_W  = (const float*)d_in[14];
    const float* df_b  = (const float*)d_in[15];
    float* out = (float*)d_out;

    k0_prep<<<1, 256>>>(Mk, e_W, a_W, f_W, df_W, v_emb, e_b, a_b);
    dim3 gt((NC + 31) / 32, DD / 32);
    k0_transpose<<<gt, dim3(32, 8)>>>(k_emb);
    dim3 g1(KT / 128, NOUT / 128);
    k1_gemm<<<g1, 256>>>();
    k2_post<<<NC / 4, 128>>>(f_b, df_b);
    k3_scan<<<BB * GG, 128>>>(q, r, Mv0);
    k4_final<<<(BB * LL) / 64, 128>>>(q, ab_W, ab_b, out);
}

// round 14
// speedup vs baseline: 1.5019x; 1.0053x over previous
#include <cuda_runtime.h>
#include <cstdint>

// Problem constants
#define BB   128      // batch
#define LL   200      // seq len
#define NC   10000    // num classes
#define DD   128      // feature dim
#define MM   64       // memory slots
#define GG   4        // m-groups in scan
#define MG   (MM/GG)  // 16 m per group
#define NOUT 512      // padded rows of Wbig (449 real)
#define KT   10112    // padded class count (79*128)
#define NTOK (BB*LL)  // 25600 tokens

// WbigT column layout (n index):
//  [0,64)    Mk logits  [64,192) e_W  [192,320) a_W  [320,448) fk  [448] df

__device__ float g_WbigT[DD * NOUT];         // [i][n]
__device__ float g_kembT[DD * KT];           // [i][c]
__device__ float g_Z[NC * NOUT];             // per-class table
__device__ float g_fWT[DD * DD];             // f_W[:, :128]^T : [i][j]
__device__ float g_ebias[2 * DD];
__device__ float g_abias[2 * DD];
__device__ float g_E[NTOK * DD];             // sigmoid'd erase gate per token
__device__ float g_A[NTOK * DD];             // tanh'd add vec per token
__device__ float g_preads[NTOK * GG * DD];   // partial reads

// --------------------------- fast math helpers ----------------------------
__device__ __forceinline__ float fsigmoid(float x) {
    return __fdividef(1.f, 1.f + __expf(-x));
}
__device__ __forceinline__ float ftanh(float x) {
    return 1.f - __fdividef(2.f, __expf(2.f * x) + 1.f);
}
__device__ __forceinline__ uint32_t smem_u32(const void* p) {
    uint32_t r;
    asm("{ .reg .u64 t; cvta.to.shared.u64 t, %1; cvt.u32.u64 %0, t; }"
        : "=r"(r) : "l"(p));
    return r;
}
__device__ __forceinline__ void cp16(uint32_t s, const void* g) {
    asm volatile("cp.async.cg.shared.global [%0], [%1], 16;" :: "r"(s), "l"(g));
}

// ---------------------------------------------------------------------------
// K0: build WbigT, fW-transpose, r-dependent biases
// ---------------------------------------------------------------------------
__global__ void k0_prep(const float* __restrict__ Mk,
                        const float* __restrict__ eW,
                        const float* __restrict__ aW,
                        const float* __restrict__ fW,
                        const float* __restrict__ dfW,
                        const float* __restrict__ vemb,
                        const float* __restrict__ eb,
                        const float* __restrict__ ab) {
    int tid = threadIdx.x; // 256
    for (int idx = tid; idx < NOUT * DD; idx += 256) {
        int n = idx & 511, i = idx >> 9;
        float v;
        if (n < 64)        v = Mk[n * DD + i];
        else if (n < 192)  v = eW[(n - 64) * DD + i];
        else if (n < 320)  v = aW[(n - 192) * DD + i];
        else if (n < 448)  v = fW[(n - 320) * (2 * DD) + DD + i];
        else if (n == 448) v = dfW[i];
        else               v = 0.f;
        g_WbigT[i * NOUT + n] = v;
    }
    for (int idx = tid; idx < DD * DD; idx += 256) {
        int i = idx >> 7, j = idx & 127;
        g_fWT[i * DD + j] = fW[j * (2 * DD) + i];
    }
    {
        int r = tid >> 7, d = tid & 127;
        float acc_e = 0.f, acc_a = 0.f;
        for (int i = 0; i < DD; i++) {
            float vv = vemb[r * DD + i];
            acc_e = fmaf(eW[d * DD + i], vv, acc_e);
            acc_a = fmaf(aW[d * DD + i], vv, acc_a);
        }
        g_ebias[tid] = acc_e + eb[d];
        g_abias[tid] = acc_a + ab[d];
    }
}

// ---------------------------------------------------------------------------
// K0t: transpose k_emb [NC,DD] -> g_kembT [DD,KT]
// ---------------------------------------------------------------------------
__global__ void k0_transpose(const float* __restrict__ kemb) {
    __shared__ float t[32][33];
    const int bx = blockIdx.x * 32, by = blockIdx.y * 32;
    const int x = threadIdx.x, y = threadIdx.y;
#pragma unroll
    for (int i = 0; i < 32; i += 8) {
        int c = bx + y + i;
        t[y + i][x] = (c < NC) ? kemb[c * DD + by + x] : 0.f;
    }
    __syncthreads();
#pragma unroll
    for (int i = 0; i < 32; i += 8)
        g_kembT[(by + y + i) * KT + bx + x] = t[x][y + i];
}

// ---------------------------------------------------------------------------
// K1: Z = k_emb @ Wbig^T   (10112 x 512 x 128), cp.async double-buffered
// ---------------------------------------------------------------------------
__global__ void __launch_bounds__(256, 2) k1_gemm() {
    __shared__ __align__(16) float As[2][32 * 128];
    __shared__ __align__(16) float Bs[2][32 * 128];
    const int cb = blockIdx.x * 128;
    const int nb = blockIdx.y * 128;
    const int tid = threadIdx.x;
    const int tx = tid & 15, ty = tid >> 4;
    const int m0 = ty * 8, n0 = tx * 8;

    float acc[8][8];
#pragma unroll
    for (int i = 0; i < 8; i++)
#pragma unroll
        for (int j = 0; j < 8; j++) acc[i][j] = 0.f;

    auto issue = [&](int buf, int ko) {
#pragma unroll
        for (int i = 0; i < 4; i++) {
            int f = tid + i * 256;
            int k = f >> 5, c4 = (f & 31) * 4;
            cp16(smem_u32(&As[buf][k * 128 + c4]),
                 &g_kembT[(ko + k) * KT + cb + c4]);
            cp16(smem_u32(&Bs[buf][k * 128 + c4]),
                 &g_WbigT[(ko + k) * NOUT + nb + c4]);
        }
        asm volatile("cp.async.commit_group;" ::: "memory");
    };

    issue(0, 0);
    for (int it = 0; it < 4; it++) {
        asm volatile("cp.async.wait_group 0;" ::: "memory");
        __syncthreads();
        if (it < 3) issue((it + 1) & 1, (it + 1) * 32);
        const float* Ab = &As[it & 1][0];
        const float* Bb = &Bs[it & 1][0];
#pragma unroll
        for (int k = 0; k < 32; k++) {
            float a[8], b[8];
            *(float4*)&a[0] = *(const float4*)&Ab[k * 128 + m0];
            *(float4*)&a[4] = *(const float4*)&Ab[k * 128 + m0 + 4];
            *(float4*)&b[0] = *(const float4*)&Bb[k * 128 + n0];
            *(float4*)&b[4] = *(const float4*)&Bb[k * 128 + n0 + 4];
#pragma unroll
            for (int i = 0; i < 8; i++)
#pragma unroll
                for (int j = 0; j < 8; j++)
                    acc[i][j] = fmaf(a[i], b[j], acc[i][j]);
        }
        __syncthreads();
    }
#pragma unroll
    for (int i = 0; i < 8; i++) {
        int c = cb + m0 + i;
        if (c < NC) {
            *(float4*)&g_Z[c * NOUT + nb + n0]     = *(float4*)&acc[i][0];
            *(float4*)&g_Z[c * NOUT + nb + n0 + 4] = *(float4*)&acc[i][4];
        }
    }
}

// ---------------------------------------------------------------------------
// K2: softmax over Z[c][0:64] only. One warp per class.
// ---------------------------------------------------------------------------
__global__ void k2_post() {
    int c = blockIdx.x * 4 + (threadIdx.x >> 5);
    int lane = threadIdx.x & 31;
    float* z = &g_Z[c * NOUT];
    float x0 = z[lane], x1 = z[lane + 32];
    float mx = fmaxf(x0, x1);
#pragma unroll
    for (int off = 16; off; off >>= 1)
        mx = fmaxf(mx, __shfl_xor_sync(0xffffffffu, mx, off));
    float e0 = __expf(x0 - mx), e1 = __expf(x1 - mx);
    float s = e0 + e1;
#pragma unroll
    for (int off = 16; off; off >>= 1)
        s += __shfl_xor_sync(0xffffffffu, s, off);
    float inv = __fdividef(1.f, s);
    z[lane] = e0 * inv;
    z[lane + 32] = e1 * inv;
}

// ---------------------------------------------------------------------------
// K_ea: per-token erase/add gates with nonlinearities applied.
// ---------------------------------------------------------------------------
__global__ void __launch_bounds__(128) k_ea(const int* __restrict__ q,
                                            const int* __restrict__ r) {
    const int d = threadIdx.x;
    const int t0 = blockIdx.x * 16;
    const float eb0 = g_ebias[d], eb1 = g_ebias[DD + d];
    const float ab0 = g_abias[d], ab1 = g_abias[DD + d];
#pragma unroll 4
    for (int tt = 0; tt < 16; tt++) {
        const int tok = t0 + tt;
        const int c = q[tok];
        const int rr = r[tok];
        float e = fsigmoid(g_Z[c * NOUT + 64 + d]  + (rr ? eb1 : eb0));
        float a = ftanh  (g_Z[c * NOUT + 192 + d] + (rr ? ab1 : ab0));
        g_E[tok * DD + d] = e;
        g_A[tok * DD + d] = a;
    }
}

// ---------------------------------------------------------------------------
// K3: sequential scan. Block = (b, m-group). Thread d owns column d, MG=16
// state rows in registers. w table staged in smem; E/A prefetched 1 step
// ahead. ZERO barriers and ZERO MUFU in the main loop.
// ---------------------------------------------------------------------------
__global__ void __launch_bounds__(128) k3_scan(const int* __restrict__ q,
                                               const float* __restrict__ Mv0) {
    __shared__ int qs[LL];
    __shared__ float wtab[LL * MG];   // 12.8 KB
    const int b = blockIdx.x >> 2;
    const int g = blockIdx.x & 3;
    const int d = threadIdx.x;

    for (int i = d; i < LL; i += 128) qs[i] = q[b * LL + i];
    __syncthreads();
    for (int idx = d; idx < LL * MG; idx += 128)
        wtab[idx] = g_Z[qs[idx >> 4] * NOUT + g * MG + (idx & 15)];

    float Mv[MG];
#pragma unroll
    for (int j = 0; j < MG; j++) Mv[j] = Mv0[(g * MG + j) * DD + d];
    __syncthreads();

    const float* Ep = &g_E[b * LL * DD + d];
    const float* Ap = &g_A[b * LL * DD + d];
    float ee = Ep[0], aa = Ap[0];
    float* outp = &g_preads[(b * LL * GG + g) * DD + d];

#pragma unroll 2
    for (int t = 0; t < LL; t++) {
        const int tn = (t < LL - 1) ? t + 1 : LL - 1;
        float ee_n = Ep[tn * DD];
        float aa_n = Ap[tn * DD];

        float r0 = 0.f, r1 = 0.f;
        const float* wp = &wtab[t * MG];
#pragma unroll
        for (int j = 0; j < MG; j += 2) {
            float w0 = wp[j], w1 = wp[j + 1];
            r0 = fmaf(w0, Mv[j], r0);
            r1 = fmaf(w1, Mv[j + 1], r1);
            Mv[j]     = fmaf(w0, fmaf(-ee, Mv[j],     aa), Mv[j]);
            Mv[j + 1] = fmaf(w1, fmaf(-ee, Mv[j + 1], aa), Mv[j + 1]);
        }
        outp[t * (GG * DD)] = r0 + r1;
        ee = ee_n; aa = aa_n;
    }
}

// ---------------------------------------------------------------------------
// K4: tiled GEMM epilogue. 25600 x 128 x 128:
//   f = tanh(reads @ fWr^T + fk(c) + f_b);  p = sigmoid(3*tanh(f.abW + ab_b) - qd(c))
// A tile = 4-group-summed preads (LDG+sum+STS); B tile = g_fWT via cp.async.
// ---------------------------------------------------------------------------
__global__ void __launch_bounds__(256, 2) k4_final(const int* __restrict__ q,
                                                   const float* __restrict__ f_b,
                                                   const float* __restrict__ abW,
                                                   const float* __restrict__ ab_b,
                                                   const float* __restrict__ df_b,
                                                   float* __restrict__ out) {
    __shared__ __align__(16) float As[32 * 128];
    __shared__ __align__(16) float Bs[32 * 128];
    const int tok0 = blockIdx.x * 128;
    const int tid = threadIdx.x;
    const int tx = tid & 15, ty = tid >> 4;
    const int m0 = ty * 8, n0 = tx * 8;

    float acc[8][8];
#pragma unroll
    for (int i = 0; i < 8; i++)
#pragma unroll
        for (int j = 0; j < 8; j++) acc[i][j] = 0.f;

    float abw[8], fb[8];
#pragma unroll
    for (int j = 0; j < 8; j++) {
        abw[j] = abW[n0 + j];
        fb[j]  = f_b[n0 + j];
    }
    const float abb = ab_b[0];
    const float dfb = df_b[0];

    for (int ko = 0; ko < DD; ko += 32) {
        // B chunk via cp.async (g_fWT rows are already [k][j])
#pragma unroll
        for (int i = 0; i < 4; i++) {
            int f = tid + i * 256;
            int k = f >> 5, c4 = (f & 31) * 4;
            cp16(smem_u32(&Bs[k * 128 + c4]), &g_fWT[(ko + k) * DD + c4]);
        }
        asm volatile("cp.async.commit_group;" ::: "memory");
        // A chunk: sum 4 group partials, store transposed [k][token]
#pragma unroll
        for (int i = 0; i < 4; i++) {
            int slot = tid + i * 256;          // 0..1023 float4 slots
            int tok = slot >> 3, i4 = slot & 7;
            const float* p = &g_preads[(tok0 + tok) * (GG * DD) + ko + i4 * 4];
            float4 v0 = *(const float4*)&p[0];
            float4 v1 = *(const float4*)&p[DD];
            float4 v2 = *(const float4*)&p[2 * DD];
            float4 v3 = *(const float4*)&p[3 * DD];
            float sx = v0.x + v1.x + v2.x + v3.x;
            float sy = v0.y + v1.y + v2.y + v3.y;
            float sz = v0.z + v1.z + v2.z + v3.z;
            float sw = v0.w + v1.w + v2.w + v3.w;
            As[(i4 * 4 + 0) * 128 + tok] = sx;
            As[(i4 * 4 + 1) * 128 + tok] = sy;
            As[(i4 * 4 + 2) * 128 + tok] = sz;
            As[(i4 * 4 + 3) * 128 + tok] = sw;
        }
        asm volatile("cp.async.wait_group 0;" ::: "memory");
        __syncthreads();
#pragma unroll
        for (int k = 0; k < 32; k++) {
            float a[8], b[8];
            *(float4*)&a[0] = *(const float4*)&As[k * 128 + m0];
            *(float4*)&a[4] = *(const float4*)&As[k * 128 + m0 + 4];
            *(float4*)&b[0] = *(const float4*)&Bs[k * 128 + n0];
            *(float4*)&b[4] = *(const float4*)&Bs[k * 128 + n0 + 4];
#pragma unroll
            for (int i = 0; i < 8; i++)
#pragma unroll
                for (int j = 0; j < 8; j++)
                    acc[i][j] = fmaf(a[i], b[j], acc[i][j]);
        }
        __syncthreads();
    }

    // Epilogue: per token row, tanh + dot with abW, reduce across tx (16 lanes)
#pragma unroll
    for (int i = 0; i < 8; i++) {
        const int tok = tok0 + m0 + i;
        const int c = q[tok];                 // uniform over the 16 tx lanes
        float part = 0.f;
#pragma unroll
        for (int j = 0; j < 8; j++) {
            float fk = g_Z[c * NOUT + 320 + n0 + j] + fb[j];
            part = fmaf(ftanh(acc[i][j] + fk), abw[j], part);
        }
        part += __shfl_down_sync(0xffffffffu, part, 8, 16);
        part += __shfl_down_sync(0xffffffffu, part, 4, 16);
        part += __shfl_down_sync(0xffffffffu, part, 2, 16);
        part += __shfl_down_sync(0xffffffffu, part, 1, 16);
        if (tx == 0) {
            float stu = ftanh(part + abb);
            float qd = ftanh(g_Z[c * NOUT + 448] + dfb);
            out[tok] = fsigmoid(3.f * stu - qd);
        }
    }
}

// ---------------------------------------------------------------------------
extern "C" void kernel_launch(void* const* d_in, const int* in_sizes, int n_in,
                              void* d_out, int out_size) {
    const int*   q     = (const int*)d_in[0];
    const int*   r     = (const int*)d_in[1];
    const float* k_emb = (const float*)d_in[2];
    const float* v_emb = (const float*)d_in[3];
    const float* Mk    = (const float*)d_in[4];
    const float* Mv0   = (const float*)d_in[5];
    const float* f_W   = (const float*)d_in[6];
    const float* f_b   = (const float*)d_in[7];
    const float* e_W   = (const float*)d_in[8];
    const float* e_b   = (const float*)d_in[9];
    const float* a_W   = (const float*)d_in[10];
    const float* a_b   = (const float*)d_in[11];
    const float* ab_W  = (const float*)d_in[12];
    const float* ab_b  = (const float*)d_in[13];
    const float* df_W  = (const float*)d_in[14];
    const float* df_b  = (const float*)d_in[15];
    float* out = (float*)d_out;

    k0_prep<<<1, 256>>>(Mk, e_W, a_W, f_W, df_W, v_emb, e_b, a_b);
    dim3 gt((NC + 31) / 32, DD / 32);
    k0_transpose<<<gt, dim3(32, 8)>>>(k_emb);
    dim3 g1(KT / 128, NOUT / 128);
    k1_gemm<<<g1, 256>>>();
    k2_post<<<NC / 4, 128>>>();
    k_ea<<<NTOK / 16, 128>>>(q, r);
    k3_scan<<<BB * GG, 128>>>(q, Mv0);
    k4_final<<<NTOK / 128, 256>>>(q, f_b, ab_W, ab_b, df_b, out);
}

// round 15
// speedup vs baseline: 1.5075x; 1.0037x over previous
#include <cuda_runtime.h>
#include <cstdint>

// Problem constants
#define BB   128      // batch
#define LL   200      // seq len
#define NC   10000    // num classes
#define DD   128      // feature dim
#define MM   64       // memory slots
#define GG   4        // m-groups in scan
#define MG   (MM/GG)  // 16 m per group
#define NOUT 512      // padded rows of Wbig (449 real)
#define KT   10112    // padded class count (79*128)
#define NTOK (BB*LL)  // 25600 tokens

// WbigT column layout (n index):
//  [0,64)    Mk logits  [64,192) e_W  [192,320) a_W  [320,448) fk  [448] df

__device__ float g_WbigT[DD * NOUT];         // [i][n]
__device__ float g_kembT[DD * KT];           // [i][c]
__device__ float g_Z[NC * NOUT];             // per-class table
__device__ float g_fWT[DD * DD];             // f_W[:, :128]^T : [i][j]
__device__ float g_ebias[2 * DD];
__device__ float g_abias[2 * DD];
__device__ float g_E[NTOK * DD];             // sigmoid'd erase gate per token
__device__ float g_A[NTOK * DD];             // tanh'd add vec per token
__device__ float g_preads[NTOK * GG * DD];   // partial reads

// --------------------------- fast math helpers ----------------------------
__device__ __forceinline__ float fsigmoid(float x) {
    return __fdividef(1.f, 1.f + __expf(-x));
}
__device__ __forceinline__ float ftanh(float x) {
    return 1.f - __fdividef(2.f, __expf(2.f * x) + 1.f);
}
__device__ __forceinline__ uint32_t smem_u32(const void* p) {
    uint32_t r;
    asm("{ .reg .u64 t; cvta.to.shared.u64 t, %1; cvt.u32.u64 %0, t; }"
        : "=r"(r) : "l"(p));
    return r;
}
__device__ __forceinline__ void cp16(uint32_t s, const void* g) {
    asm volatile("cp.async.cg.shared.global [%0], [%1], 16;" :: "r"(s), "l"(g));
}

// ---------------------------------------------------------------------------
// K0: build WbigT, fW-transpose, r-dependent biases
// ---------------------------------------------------------------------------
__global__ void k0_prep(const float* __restrict__ Mk,
                        const float* __restrict__ eW,
                        const float* __restrict__ aW,
                        const float* __restrict__ fW,
                        const float* __restrict__ dfW,
                        const float* __restrict__ vemb,
                        const float* __restrict__ eb,
                        const float* __restrict__ ab) {
    int tid = threadIdx.x; // 256
    for (int idx = tid; idx < NOUT * DD; idx += 256) {
        int n = idx & 511, i = idx >> 9;
        float v;
        if (n < 64)        v = Mk[n * DD + i];
        else if (n < 192)  v = eW[(n - 64) * DD + i];
        else if (n < 320)  v = aW[(n - 192) * DD + i];
        else if (n < 448)  v = fW[(n - 320) * (2 * DD) + DD + i];
        else if (n == 448) v = dfW[i];
        else               v = 0.f;
        g_WbigT[i * NOUT + n] = v;
    }
    for (int idx = tid; idx < DD * DD; idx += 256) {
        int i = idx >> 7, j = idx & 127;
        g_fWT[i * DD + j] = fW[j * (2 * DD) + i];
    }
    {
        int r = tid >> 7, d = tid & 127;
        float acc_e = 0.f, acc_a = 0.f;
        for (int i = 0; i < DD; i++) {
            float vv = vemb[r * DD + i];
            acc_e = fmaf(eW[d * DD + i], vv, acc_e);
            acc_a = fmaf(aW[d * DD + i], vv, acc_a);
        }
        g_ebias[tid] = acc_e + eb[d];
        g_abias[tid] = acc_a + ab[d];
    }
}

// ---------------------------------------------------------------------------
// K0t: transpose k_emb [NC,DD] -> g_kembT [DD,KT]
// ---------------------------------------------------------------------------
__global__ void k0_transpose(const float* __restrict__ kemb) {
    __shared__ float t[32][33];
    const int bx = blockIdx.x * 32, by = blockIdx.y * 32;
    const int x = threadIdx.x, y = threadIdx.y;
#pragma unroll
    for (int i = 0; i < 32; i += 8) {
        int c = bx + y + i;
        t[y + i][x] = (c < NC) ? kemb[c * DD + by + x] : 0.f;
    }
    __syncthreads();
#pragma unroll
    for (int i = 0; i < 32; i += 8)
        g_kembT[(by + y + i) * KT + bx + x] = t[x][y + i];
}

// ---------------------------------------------------------------------------
// K1: Z = k_emb @ Wbig^T   (10112 x 512 x 128), cp.async double-buffered
// ---------------------------------------------------------------------------
__global__ void __launch_bounds__(256, 2) k1_gemm() {
    __shared__ __align__(16) float As[2][32 * 128];
    __shared__ __align__(16) float Bs[2][32 * 128];
    const int cb = blockIdx.x * 128;
    const int nb = blockIdx.y * 128;
    const int tid = threadIdx.x;
    const int tx = tid & 15, ty = tid >> 4;
    const int m0 = ty * 8, n0 = tx * 8;

    float acc[8][8];
#pragma unroll
    for (int i = 0; i < 8; i++)
#pragma unroll
        for (int j = 0; j < 8; j++) acc[i][j] = 0.f;

    auto issue = [&](int buf, int ko) {
#pragma unroll
        for (int i = 0; i < 4; i++) {
            int f = tid + i * 256;
            int k = f >> 5, c4 = (f & 31) * 4;
            cp16(smem_u32(&As[buf][k * 128 + c4]),
                 &g_kembT[(ko + k) * KT + cb + c4]);
            cp16(smem_u32(&Bs[buf][k * 128 + c4]),
                 &g_WbigT[(ko + k) * NOUT + nb + c4]);
        }
        asm volatile("cp.async.commit_group;" ::: "memory");
    };

    issue(0, 0);
    for (int it = 0; it < 4; it++) {
        asm volatile("cp.async.wait_group 0;" ::: "memory");
        __syncthreads();
        if (it < 3) issue((it + 1) & 1, (it + 1) * 32);
        const float* Ab = &As[it & 1][0];
        const float* Bb = &Bs[it & 1][0];
#pragma unroll
        for (int k = 0; k < 32; k++) {
            float a[8], b[8];
            *(float4*)&a[0] = *(const float4*)&Ab[k * 128 + m0];
            *(float4*)&a[4] = *(const float4*)&Ab[k * 128 + m0 + 4];
            *(float4*)&b[0] = *(const float4*)&Bb[k * 128 + n0];
            *(float4*)&b[4] = *(const float4*)&Bb[k * 128 + n0 + 4];
#pragma unroll
            for (int i = 0; i < 8; i++)
#pragma unroll
                for (int j = 0; j < 8; j++)
                    acc[i][j] = fmaf(a[i], b[j], acc[i][j]);
        }
        __syncthreads();
    }
#pragma unroll
    for (int i = 0; i < 8; i++) {
        int c = cb + m0 + i;
        if (c < NC) {
            *(float4*)&g_Z[c * NOUT + nb + n0]     = *(float4*)&acc[i][0];
            *(float4*)&g_Z[c * NOUT + nb + n0 + 4] = *(float4*)&acc[i][4];
        }
    }
}

// ---------------------------------------------------------------------------
// K2: softmax over Z[c][0:64] only. One warp per class.
// ---------------------------------------------------------------------------
__global__ void k2_post() {
    int c = blockIdx.x * 4 + (threadIdx.x >> 5);
    int lane = threadIdx.x & 31;
    float* z = &g_Z[c * NOUT];
    float x0 = z[lane], x1 = z[lane + 32];
    float mx = fmaxf(x0, x1);
#pragma unroll
    for (int off = 16; off; off >>= 1)
        mx = fmaxf(mx, __shfl_xor_sync(0xffffffffu, mx, off));
    float e0 = __expf(x0 - mx), e1 = __expf(x1 - mx);
    float s = e0 + e1;
#pragma unroll
    for (int off = 16; off; off >>= 1)
        s += __shfl_xor_sync(0xffffffffu, s, off);
    float inv = __fdividef(1.f, s);
    z[lane] = e0 * inv;
    z[lane + 32] = e1 * inv;
}

// ---------------------------------------------------------------------------
// K_ea: per-token erase/add gates with nonlinearities applied.
// ---------------------------------------------------------------------------
__global__ void __launch_bounds__(128) k_ea(const int* __restrict__ q,
                                            const int* __restrict__ r) {
    const int d = threadIdx.x;
    const int t0 = blockIdx.x * 16;
    const float eb0 = g_ebias[d], eb1 = g_ebias[DD + d];
    const float ab0 = g_abias[d], ab1 = g_abias[DD + d];
#pragma unroll 4
    for (int tt = 0; tt < 16; tt++) {
        const int tok = t0 + tt;
        const int c = q[tok];
        const int rr = r[tok];
        float e = fsigmoid(g_Z[c * NOUT + 64 + d]  + (rr ? eb1 : eb0));
        float a = ftanh  (g_Z[c * NOUT + 192 + d] + (rr ? ab1 : ab0));
        g_E[tok * DD + d] = e;
        g_A[tok * DD + d] = a;
    }
}

// ---------------------------------------------------------------------------
// K3: sequential scan. Block = (b, m-group). Thread d owns column d, MG=16
// state rows in registers. w table staged in smem; E/A prefetched 1 step
// ahead. ZERO barriers and ZERO MUFU in the main loop.
// ---------------------------------------------------------------------------
__global__ void __launch_bounds__(128) k3_scan(const int* __restrict__ q,
                                               const float* __restrict__ Mv0) {
    __shared__ int qs[LL];
    __shared__ float wtab[LL * MG];   // 12.8 KB
    const int b = blockIdx.x >> 2;
    const int g = blockIdx.x & 3;
    const int d = threadIdx.x;

    for (int i = d; i < LL; i += 128) qs[i] = q[b * LL + i];
    __syncthreads();
    for (int idx = d; idx < LL * MG; idx += 128)
        wtab[idx] = g_Z[qs[idx >> 4] * NOUT + g * MG + (idx & 15)];

    float Mv[MG];
#pragma unroll
    for (int j = 0; j < MG; j++) Mv[j] = Mv0[(g * MG + j) * DD + d];
    __syncthreads();

    const float* Ep = &g_E[b * LL * DD + d];
    const float* Ap = &g_A[b * LL * DD + d];
    float ee = Ep[0], aa = Ap[0];
    float* outp = &g_preads[(b * LL * GG + g) * DD + d];

#pragma unroll 2
    for (int t = 0; t < LL; t++) {
        const int tn = (t < LL - 1) ? t + 1 : LL - 1;
        float ee_n = Ep[tn * DD];
        float aa_n = Ap[tn * DD];

        float r0 = 0.f, r1 = 0.f;
        const float* wp = &wtab[t * MG];
#pragma unroll
        for (int j = 0; j < MG; j += 2) {
            float w0 = wp[j], w1 = wp[j + 1];
            r0 = fmaf(w0, Mv[j], r0);
            r1 = fmaf(w1, Mv[j + 1], r1);
            Mv[j]     = fmaf(w0, fmaf(-ee, Mv[j],     aa), Mv[j]);
            Mv[j + 1] = fmaf(w1, fmaf(-ee, Mv[j + 1], aa), Mv[j + 1]);
        }
        outp[t * (GG * DD)] = r0 + r1;
        ee = ee_n; aa = aa_n;
    }
}

// ---------------------------------------------------------------------------
// K4: tiled GEMM epilogue. 25600 x 128 x 128:
//   f = tanh(reads @ fWr^T + fk(c) + f_b);  p = sigmoid(3*tanh(f.abW + ab_b) - qd(c))
// A tile = 4-group-summed preads (LDG+sum+STS); B tile = g_fWT via cp.async.
// ---------------------------------------------------------------------------
__global__ void __launch_bounds__(256, 2) k4_final(const int* __restrict__ q,
                                                   const float* __restrict__ f_b,
                                                   const float* __restrict__ abW,
                                                   const float* __restrict__ ab_b,
                                                   const float* __restrict__ df_b,
                                                   float* __restrict__ out) {
    __shared__ __align__(16) float As[32 * 128];
    __shared__ __align__(16) float Bs[32 * 128];
    const int tok0 = blockIdx.x * 128;
    const int tid = threadIdx.x;
    const int tx = tid & 15, ty = tid >> 4;
    const int m0 = ty * 8, n0 = tx * 8;

    float acc[8][8];
#pragma unroll
    for (int i = 0; i < 8; i++)
#pragma unroll
        for (int j = 0; j < 8; j++) acc[i][j] = 0.f;

    float abw[8], fb[8];
#pragma unroll
    for (int j = 0; j < 8; j++) {
        abw[j] = abW[n0 + j];
        fb[j]  = f_b[n0 + j];
    }
    const float abb = ab_b[0];
    const float dfb = df_b[0];

    for (int ko = 0; ko < DD; ko += 32) {
        // B chunk via cp.async (g_fWT rows are already [k][j])
#pragma unroll
        for (int i = 0; i < 4; i++) {
            int f = tid + i * 256;
            int k = f >> 5, c4 = (f & 31) * 4;
            cp16(smem_u32(&Bs[k * 128 + c4]), &g_fWT[(ko + k) * DD + c4]);
        }
        asm volatile("cp.async.commit_group;" ::: "memory");
        // A chunk: sum 4 group partials, store transposed [k][token]
#pragma unroll
        for (int i = 0; i < 4; i++) {
            int slot = tid + i * 256;          // 0..1023 float4 slots
            int tok = slot >> 3, i4 = slot & 7;
            const float* p = &g_preads[(tok0 + tok) * (GG * DD) + ko + i4 * 4];
            float4 v0 = *(const float4*)&p[0];
            float4 v1 = *(const float4*)&p[DD];
            float4 v2 = *(const float4*)&p[2 * DD];
            float4 v3 = *(const float4*)&p[3 * DD];
            float sx = v0.x + v1.x + v2.x + v3.x;
            float sy = v0.y + v1.y + v2.y + v3.y;
            float sz = v0.z + v1.z + v2.z + v3.z;
            float sw = v0.w + v1.w + v2.w + v3.w;
            As[(i4 * 4 + 0) * 128 + tok] = sx;
            As[(i4 * 4 + 1) * 128 + tok] = sy;
            As[(i4 * 4 + 2) * 128 + tok] = sz;
            As[(i4 * 4 + 3) * 128 + tok] = sw;
        }
        asm volatile("cp.async.wait_group 0;" ::: "memory");
        __syncthreads();
#pragma unroll
        for (int k = 0; k < 32; k++) {
            float a[8], b[8];
            *(float4*)&a[0] = *(const float4*)&As[k * 128 + m0];
            *(float4*)&a[4] = *(const float4*)&As[k * 128 + m0 + 4];
            *(float4*)&b[0] = *(const float4*)&Bs[k * 128 + n0];
            *(float4*)&b[4] = *(const float4*)&Bs[k * 128 + n0 + 4];
#pragma unroll
            for (int i = 0; i < 8; i++)
#pragma unroll
                for (int j = 0; j < 8; j++)
                    acc[i][j] = fmaf(a[i], b[j], acc[i][j]);
        }
        __syncthreads();
    }

    // Epilogue: per token row, tanh + dot with abW, reduce across tx (16 lanes)
#pragma unroll
    for (int i = 0; i < 8; i++) {
        const int tok = tok0 + m0 + i;
        const int c = q[tok];                 // uniform over the 16 tx lanes
        float part = 0.f;
#pragma unroll
        for (int j = 0; j < 8; j++) {
            float fk = g_Z[c * NOUT + 320 + n0 + j] + fb[j];
            part = fmaf(ftanh(acc[i][j] + fk), abw[j], part);
        }
        part += __shfl_down_sync(0xffffffffu, part, 8, 16);
        part += __shfl_down_sync(0xffffffffu, part, 4, 16);
        part += __shfl_down_sync(0xffffffffu, part, 2, 16);
        part += __shfl_down_sync(0xffffffffu, part, 1, 16);
        if (tx == 0) {
            float stu = ftanh(part + abb);
            float qd = ftanh(g_Z[c * NOUT + 448] + dfb);
            out[tok] = fsigmoid(3.f * stu - qd);
        }
    }
}

// ---------------------------------------------------------------------------
extern "C" void kernel_launch(void* const* d_in, const int* in_sizes, int n_in,
                              void* d_out, int out_size) {
    const int*   q     = (const int*)d_in[0];
    const int*   r     = (const int*)d_in[1];
    const float* k_emb = (const float*)d_in[2];
    const float* v_emb = (const float*)d_in[3];
    const float* Mk    = (const float*)d_in[4];
    const float* Mv0   = (const float*)d_in[5];
    const float* f_W   = (const float*)d_in[6];
    const float* f_b   = (const float*)d_in[7];
    const float* e_W   = (const float*)d_in[8];
    const float* e_b   = (const float*)d_in[9];
    const float* a_W   = (const float*)d_in[10];
    const float* a_b   = (const float*)d_in[11];
    const float* ab_W  = (const float*)d_in[12];
    const float* ab_b  = (const float*)d_in[13];
    const float* df_W  = (const float*)d_in[14];
    const float* df_b  = (const float*)d_in[15];
    float* out = (float*)d_out;

    k0_prep<<<1, 256>>>(Mk, e_W, a_W, f_W, df_W, v_emb, e_b, a_b);
    dim3 gt((NC + 31) / 32, DD / 32);
    k0_transpose<<<gt, dim3(32, 8)>>>(k_emb);
    dim3 g1(KT / 128, NOUT / 128);
    k1_gemm<<<g1, 256>>>();
    k2_post<<<NC / 4, 128>>>();
    k_ea<<<NTOK / 16, 128>>>(q, r);
    k3_scan<<<BB * GG, 128>>>(q, Mv0);
    k4_final<<<NTOK / 128, 256>>>(q, f_b, ab_W, ab_b, df_b, out);
}

// round 16
// speedup vs baseline: 1.5107x; 1.0021x over previous
#include <cuda_runtime.h>
#include <cstdint>

// Problem constants
#define BB   128      // batch
#define LL   200      // seq len
#define NC   10000    // num classes
#define DD   128      // feature dim
#define MM   64       // memory slots
#define GG   4        // m-groups in scan
#define MG   (MM/GG)  // 16 m per group
#define NOUT 512      // padded rows of Wbig (449 real)
#define KT   10112    // padded class count (79*128)
#define NTOK (BB*LL)  // 25600 tokens

// WbigT column layout (n index):
//  [0,64)    Mk logits  [64,192) e_W  [192,320) a_W  [320,448) fk  [448] df

__device__ float g_WbigT[DD * NOUT];         // [i][n]
__device__ float g_kembT[DD * KT];           // [i][c]
__device__ float g_Z[NC * NOUT];             // per-class table
__device__ float g_fWT[DD * DD];             // f_W[:, :128]^T : [i][j]
__device__ float g_ebias[2 * DD];
__device__ float g_abias[2 * DD];
__device__ float g_E[NTOK * DD];             // sigmoid'd erase gate per token
__device__ float g_A[NTOK * DD];             // tanh'd add vec per token
__device__ float g_preads[NTOK * GG * DD];   // partial reads

// --------------------------- fast math helpers ----------------------------
__device__ __forceinline__ float fsigmoid(float x) {
    return __fdividef(1.f, 1.f + __expf(-x));
}
__device__ __forceinline__ float ftanh(float x) {
    return 1.f - __fdividef(2.f, __expf(2.f * x) + 1.f);
}
__device__ __forceinline__ uint32_t smem_u32(const void* p) {
    uint32_t r;
    asm("{ .reg .u64 t; cvta.to.shared.u64 t, %1; cvt.u32.u64 %0, t; }"
        : "=r"(r) : "l"(p));
    return r;
}
__device__ __forceinline__ void cp16(uint32_t s, const void* g) {
    asm volatile("cp.async.cg.shared.global [%0], [%1], 16;" :: "r"(s), "l"(g));
}

// ---------------------------------------------------------------------------
// K0: build WbigT, fW-transpose, r-dependent biases
// ---------------------------------------------------------------------------
__global__ void k0_prep(const float* __restrict__ Mk,
                        const float* __restrict__ eW,
                        const float* __restrict__ aW,
                        const float* __restrict__ fW,
                        const float* __restrict__ dfW,
                        const float* __restrict__ vemb,
                        const float* __restrict__ eb,
                        const float* __restrict__ ab) {
    int tid = threadIdx.x; // 256
    for (int idx = tid; idx < NOUT * DD; idx += 256) {
        int n = idx & 511, i = idx >> 9;
        float v;
        if (n < 64)        v = Mk[n * DD + i];
        else if (n < 192)  v = eW[(n - 64) * DD + i];
        else if (n < 320)  v = aW[(n - 192) * DD + i];
        else if (n < 448)  v = fW[(n - 320) * (2 * DD) + DD + i];
        else if (n == 448) v = dfW[i];
        else               v = 0.f;
        g_WbigT[i * NOUT + n] = v;
    }
    for (int idx = tid; idx < DD * DD; idx += 256) {
        int i = idx >> 7, j = idx & 127;
        g_fWT[i * DD + j] = fW[j * (2 * DD) + i];
    }
    {
        int r = tid >> 7, d = tid & 127;
        float acc_e = 0.f, acc_a = 0.f;
        for (int i = 0; i < DD; i++) {
            float vv = vemb[r * DD + i];
            acc_e = fmaf(eW[d * DD + i], vv, acc_e);
            acc_a = fmaf(aW[d * DD + i], vv, acc_a);
        }
        g_ebias[tid] = acc_e + eb[d];
        g_abias[tid] = acc_a + ab[d];
    }
}

// ---------------------------------------------------------------------------
// K0t: transpose k_emb [NC,DD] -> g_kembT [DD,KT]
// ---------------------------------------------------------------------------
__global__ void k0_transpose(const float* __restrict__ kemb) {
    __shared__ float t[32][33];
    const int bx = blockIdx.x * 32, by = blockIdx.y * 32;
    const int x = threadIdx.x, y = threadIdx.y;
#pragma unroll
    for (int i = 0; i < 32; i += 8) {
        int c = bx + y + i;
        t[y + i][x] = (c < NC) ? kemb[c * DD + by + x] : 0.f;
    }
    __syncthreads();
#pragma unroll
    for (int i = 0; i < 32; i += 8)
        g_kembT[(by + y + i) * KT + bx + x] = t[x][y + i];
}

// ---------------------------------------------------------------------------
// K1: Z = k_emb @ Wbig^T   (10112 x 512 x 128), cp.async double-buffered
// ---------------------------------------------------------------------------
__global__ void __launch_bounds__(256, 2) k1_gemm() {
    __shared__ __align__(16) float As[2][32 * 128];
    __shared__ __align__(16) float Bs[2][32 * 128];
    const int cb = blockIdx.x * 128;
    const int nb = blockIdx.y * 128;
    const int tid = threadIdx.x;
    const int tx = tid & 15, ty = tid >> 4;
    const int m0 = ty * 8, n0 = tx * 8;

    float acc[8][8];
#pragma unroll
    for (int i = 0; i < 8; i++)
#pragma unroll
        for (int j = 0; j < 8; j++) acc[i][j] = 0.f;

    auto issue = [&](int buf, int ko) {
#pragma unroll
        for (int i = 0; i < 4; i++) {
            int f = tid + i * 256;
            int k = f >> 5, c4 = (f & 31) * 4;
            cp16(smem_u32(&As[buf][k * 128 + c4]),
                 &g_kembT[(ko + k) * KT + cb + c4]);
            cp16(smem_u32(&Bs[buf][k * 128 + c4]),
                 &g_WbigT[(ko + k) * NOUT + nb + c4]);
        }
        asm volatile("cp.async.commit_group;" ::: "memory");
    };

    issue(0, 0);
    for (int it = 0; it < 4; it++) {
        asm volatile("cp.async.wait_group 0;" ::: "memory");
        __syncthreads();
        if (it < 3) issue((it + 1) & 1, (it + 1) * 32);
        const float* Ab = &As[it & 1][0];
        const float* Bb = &Bs[it & 1][0];
#pragma unroll
        for (int k = 0; k < 32; k++) {
            float a[8], b[8];
            *(float4*)&a[0] = *(const float4*)&Ab[k * 128 + m0];
            *(float4*)&a[4] = *(const float4*)&Ab[k * 128 + m0 + 4];
            *(float4*)&b[0] = *(const float4*)&Bb[k * 128 + n0];
            *(float4*)&b[4] = *(const float4*)&Bb[k * 128 + n0 + 4];
#pragma unroll
            for (int i = 0; i < 8; i++)
#pragma unroll
                for (int j = 0; j < 8; j++)
                    acc[i][j] = fmaf(a[i], b[j], acc[i][j]);
        }
        __syncthreads();
    }
#pragma unroll
    for (int i = 0; i < 8; i++) {
        int c = cb + m0 + i;
        if (c < NC) {
            *(float4*)&g_Z[c * NOUT + nb + n0]     = *(float4*)&acc[i][0];
            *(float4*)&g_Z[c * NOUT + nb + n0 + 4] = *(float4*)&acc[i][4];
        }
    }
}

// ---------------------------------------------------------------------------
// K2: softmax over Z[c][0:64] only. One warp per class.
// ---------------------------------------------------------------------------
__global__ void k2_post() {
    int c = blockIdx.x * 4 + (threadIdx.x >> 5);
    int lane = threadIdx.x & 31;
    float* z = &g_Z[c * NOUT];
    float x0 = z[lane], x1 = z[lane + 32];
    float mx = fmaxf(x0, x1);
#pragma unroll
    for (int off = 16; off; off >>= 1)
        mx = fmaxf(mx, __shfl_xor_sync(0xffffffffu, mx, off));
    float e0 = __expf(x0 - mx), e1 = __expf(x1 - mx);
    float s = e0 + e1;
#pragma unroll
    for (int off = 16; off; off >>= 1)
        s += __shfl_xor_sync(0xffffffffu, s, off);
    float inv = __fdividef(1.f, s);
    z[lane] = e0 * inv;
    z[lane + 32] = e1 * inv;
}

// ---------------------------------------------------------------------------
// K_ea: per-token erase/add gates with nonlinearities applied.
// ---------------------------------------------------------------------------
__global__ void __launch_bounds__(128) k_ea(const int* __restrict__ q,
                                            const int* __restrict__ r) {
    const int d = threadIdx.x;
    const int t0 = blockIdx.x * 16;
    const float eb0 = g_ebias[d], eb1 = g_ebias[DD + d];
    const float ab0 = g_abias[d], ab1 = g_abias[DD + d];
#pragma unroll 4
    for (int tt = 0; tt < 16; tt++) {
        const int tok = t0 + tt;
        const int c = q[tok];
        const int rr = r[tok];
        float e = fsigmoid(g_Z[c * NOUT + 64 + d]  + (rr ? eb1 : eb0));
        float a = ftanh  (g_Z[c * NOUT + 192 + d] + (rr ? ab1 : ab0));
        g_E[tok * DD + d] = e;
        g_A[tok * DD + d] = a;
    }
}

// ---------------------------------------------------------------------------
// K3: sequential scan. Block = (b, m-group). Thread d owns column d, MG=16
// state rows in registers. w table staged in smem; E/A prefetched 1 step
// ahead. ZERO barriers and ZERO MUFU in the main loop.
// ---------------------------------------------------------------------------
__global__ void __launch_bounds__(128) k3_scan(const int* __restrict__ q,
                                               const float* __restrict__ Mv0) {
    __shared__ int qs[LL];
    __shared__ float wtab[LL * MG];   // 12.8 KB
    const int b = blockIdx.x >> 2;
    const int g = blockIdx.x & 3;
    const int d = threadIdx.x;

    for (int i = d; i < LL; i += 128) qs[i] = q[b * LL + i];
    __syncthreads();
    for (int idx = d; idx < LL * MG; idx += 128)
        wtab[idx] = g_Z[qs[idx >> 4] * NOUT + g * MG + (idx & 15)];

    float Mv[MG];
#pragma unroll
    for (int j = 0; j < MG; j++) Mv[j] = Mv0[(g * MG + j) * DD + d];
    __syncthreads();

    const float* Ep = &g_E[b * LL * DD + d];
    const float* Ap = &g_A[b * LL * DD + d];
    float ee = Ep[0], aa = Ap[0];
    float* outp = &g_preads[(b * LL * GG + g) * DD + d];

#pragma unroll 2
    for (int t = 0; t < LL; t++) {
        const int tn = (t < LL - 1) ? t + 1 : LL - 1;
        float ee_n = Ep[tn * DD];
        float aa_n = Ap[tn * DD];

        float r0 = 0.f, r1 = 0.f;
        const float* wp = &wtab[t * MG];
#pragma unroll
        for (int j = 0; j < MG; j += 2) {
            float w0 = wp[j], w1 = wp[j + 1];
            r0 = fmaf(w0, Mv[j], r0);
            r1 = fmaf(w1, Mv[j + 1], r1);
            Mv[j]     = fmaf(w0, fmaf(-ee, Mv[j],     aa), Mv[j]);
            Mv[j + 1] = fmaf(w1, fmaf(-ee, Mv[j + 1], aa), Mv[j + 1]);
        }
        outp[t * (GG * DD)] = r0 + r1;
        ee = ee_n; aa = aa_n;
    }
}

// ---------------------------------------------------------------------------
// K4: tiled GEMM epilogue. 25600 x 128 x 128:
//   f = tanh(reads @ fWr^T + fk(c) + f_b);  p = sigmoid(3*tanh(f.abW + ab_b) - qd(c))
// A tile = 4-group-summed preads (LDG+sum+STS); B tile = g_fWT via cp.async.
// ---------------------------------------------------------------------------
__global__ void __launch_bounds__(256, 2) k4_final(const int* __restrict__ q,
                                                   const float* __restrict__ f_b,
                                                   const float* __restrict__ abW,
                                                   const float* __restrict__ ab_b,
                                                   const float* __restrict__ df_b,
                                                   float* __restrict__ out) {
    __shared__ __align__(16) float As[32 * 128];
    __shared__ __align__(16) float Bs[32 * 128];
    const int tok0 = blockIdx.x * 128;
    const int tid = threadIdx.x;
    const int tx = tid & 15, ty = tid >> 4;
    const int m0 = ty * 8, n0 = tx * 8;

    float acc[8][8];
#pragma unroll
    for (int i = 0; i < 8; i++)
#pragma unroll
        for (int j = 0; j < 8; j++) acc[i][j] = 0.f;

    float abw[8], fb[8];
#pragma unroll
    for (int j = 0; j < 8; j++) {
        abw[j] = abW[n0 + j];
        fb[j]  = f_b[n0 + j];
    }
    const float abb = ab_b[0];
    const float dfb = df_b[0];

    for (int ko = 0; ko < DD; ko += 32) {
        // B chunk via cp.async (g_fWT rows are already [k][j])
#pragma unroll
        for (int i = 0; i < 4; i++) {
            int f = tid + i * 256;
            int k = f >> 5, c4 = (f & 31) * 4;
            cp16(smem_u32(&Bs[k * 128 + c4]), &g_fWT[(ko + k) * DD + c4]);
        }
        asm volatile("cp.async.commit_group;" ::: "memory");
        // A chunk: sum 4 group partials, store transposed [k][token]
#pragma unroll
        for (int i = 0; i < 4; i++) {
            int slot = tid + i * 256;          // 0..1023 float4 slots
            int tok = slot >> 3, i4 = slot & 7;
            const float* p = &g_preads[(tok0 + tok) * (GG * DD) + ko + i4 * 4];
            float4 v0 = *(const float4*)&p[0];
            float4 v1 = *(const float4*)&p[DD];
            float4 v2 = *(const float4*)&p[2 * DD];
            float4 v3 = *(const float4*)&p[3 * DD];
            float sx = v0.x + v1.x + v2.x + v3.x;
            float sy = v0.y + v1.y + v2.y + v3.y;
            float sz = v0.z + v1.z + v2.z + v3.z;
            float sw = v0.w + v1.w + v2.w + v3.w;
            As[(i4 * 4 + 0) * 128 + tok] = sx;
            As[(i4 * 4 + 1) * 128 + tok] = sy;
            As[(i4 * 4 + 2) * 128 + tok] = sz;
            As[(i4 * 4 + 3) * 128 + tok] = sw;
        }
        asm volatile("cp.async.wait_group 0;" ::: "memory");
        __syncthreads();
#pragma unroll
        for (int k = 0; k < 32; k++) {
            float a[8], b[8];
            *(float4*)&a[0] = *(const float4*)&As[k * 128 + m0];
            *(float4*)&a[4] = *(const float4*)&As[k * 128 + m0 + 4];
            *(float4*)&b[0] = *(const float4*)&Bs[k * 128 + n0];
            *(float4*)&b[4] = *(const float4*)&Bs[k * 128 + n0 + 4];
#pragma unroll
            for (int i = 0; i < 8; i++)
#pragma unroll
                for (int j = 0; j < 8; j++)
                    acc[i][j] = fmaf(a[i], b[j], acc[i][j]);
        }
        __syncthreads();
    }

    // Epilogue: per token row, tanh + dot with abW, reduce across tx (16 lanes)
#pragma unroll
    for (int i = 0; i < 8; i++) {
        const int tok = tok0 + m0 + i;
        const int c = q[tok];                 // uniform over the 16 tx lanes
        float part = 0.f;
#pragma unroll
        for (int j = 0; j < 8; j++) {
            float fk = g_Z[c * NOUT + 320 + n0 + j] + fb[j];
            part = fmaf(ftanh(acc[i][j] + fk), abw[j], part);
        }
        part += __shfl_down_sync(0xffffffffu, part, 8, 16);
        part += __shfl_down_sync(0xffffffffu, part, 4, 16);
        part += __shfl_down_sync(0xffffffffu, part, 2, 16);
        part += __shfl_down_sync(0xffffffffu, part, 1, 16);
        if (tx == 0) {
            float stu = ftanh(part + abb);
            float qd = ftanh(g_Z[c * NOUT + 448] + dfb);
            out[tok] = fsigmoid(3.f * stu - qd);
        }
    }
}

// ---------------------------------------------------------------------------
extern "C" void kernel_launch(void* const* d_in, const int* in_sizes, int n_in,
                              void* d_out, int out_size) {
    const int*   q     = (const int*)d_in[0];
    const int*   r     = (const int*)d_in[1];
    const float* k_emb = (const float*)d_in[2];
    const float* v_emb = (const float*)d_in[3];
    const float* Mk    = (const float*)d_in[4];
    const float* Mv0   = (const float*)d_in[5];
    const float* f_W   = (const float*)d_in[6];
    const float* f_b   = (const float*)d_in[7];
    const float* e_W   = (const float*)d_in[8];
    const float* e_b   = (const float*)d_in[9];
    const float* a_W   = (const float*)d_in[10];
    const float* a_b   = (const float*)d_in[11];
    const float* ab_W  = (const float*)d_in[12];
    const float* ab_b  = (const float*)d_in[13];
    const float* df_W  = (const float*)d_in[14];
    const float* df_b  = (const float*)d_in[15];
    float* out = (float*)d_out;

    k0_prep<<<1, 256>>>(Mk, e_W, a_W, f_W, df_W, v_emb, e_b, a_b);
    dim3 gt((NC + 31) / 32, DD / 32);
    k0_transpose<<<gt, dim3(32, 8)>>>(k_emb);
    dim3 g1(KT / 128, NOUT / 128);
    k1_gemm<<<g1, 256>>>();
    k2_post<<<NC / 4, 128>>>();
    k_ea<<<NTOK / 16, 128>>>(q, r);
    k3_scan<<<BB * GG, 128>>>(q, Mv0);
    k4_final<<<NTOK / 128, 256>>>(q, f_b, ab_W, ab_b, df_b, out);
}

// round 17
// speedup vs baseline: 2.1043x; 1.3929x over previous
#include <cuda_runtime.h>
#include <cstdint>

// Problem constants
#define BB   128      // batch
#define LL   200      // seq len
#define NC   10000    // num classes
#define DD   128      // feature dim
#define MM   64       // memory slots
#define GG   4        // m-groups in scan
#define MG   (MM/GG)  // 16 m per group
#define NOUT 512      // padded rows of Wbig (449 real)
#define KT   10112    // padded class count (79*128)
#define NTOK (BB*LL)  // 25600 tokens

// WbigT column layout (n index):
//  [0,64) Mk logits  [64,192) e_W  [192,320) a_W  [320,448) fk  [448] df

__device__ float g_WbigT[DD * NOUT];         // [i][n]
__device__ float g_kembT[DD * KT];           // [i][c]
__device__ float g_Z[NC * NOUT];             // per-class table
__device__ float g_fWT[DD * DD];             // f_W[:, :128]^T : [i][j]
__device__ float g_ebias[2 * DD];
__device__ float g_abias[2 * DD];
__device__ float g_E[NTOK * DD];             // sigmoid'd erase gate per token
__device__ float g_A[NTOK * DD];             // tanh'd add vec per token
__device__ float g_Wg[BB * GG * LL * MG];    // softmaxed w, [b][g][t][m] (6.5 MB)
__device__ float g_preads[NTOK * GG * DD];   // partial reads (52 MB)

// --------------------------- fast math helpers ----------------------------
__device__ __forceinline__ float fsigmoid(float x) {
    return __fdividef(1.f, 1.f + __expf(-x));
}
__device__ __forceinline__ float ftanh(float x) {
    return 1.f - __fdividef(2.f, __expf(2.f * x) + 1.f);
}
__device__ __forceinline__ uint32_t smem_u32(const void* p) {
    uint32_t r;
    asm("{ .reg .u64 t; cvta.to.shared.u64 t, %1; cvt.u32.u64 %0, t; }"
        : "=r"(r) : "l"(p));
    return r;
}
__device__ __forceinline__ void cp16(uint32_t s, const void* g) {
    asm volatile("cp.async.cg.shared.global [%0], [%1], 16;" :: "r"(s), "l"(g));
}

// ---------------------------------------------------------------------------
// K0: build WbigT + fWT (grid-strided, 64 blocks); block 0 also computes the
// r-dependent biases with warp-coalesced float4 row reads + shfl reduction.
// ---------------------------------------------------------------------------
__global__ void __launch_bounds__(256) k0_prep(const float* __restrict__ Mk,
                        const float* __restrict__ eW,
                        const float* __restrict__ aW,
                        const float* __restrict__ fW,
                        const float* __restrict__ dfW,
                        const float* __restrict__ vemb,
                        const float* __restrict__ eb,
                        const float* __restrict__ ab) {
    const int gtid = blockIdx.x * 256 + threadIdx.x;
    const int gstr = gridDim.x * 256;
    for (int idx = gtid; idx < NOUT * DD; idx += gstr) {
        int n = idx & 511, i = idx >> 9;
        float v;
        if (n < 64)        v = Mk[n * DD + i];
        else if (n < 192)  v = eW[(n - 64) * DD + i];
        else if (n < 320)  v = aW[(n - 192) * DD + i];
        else if (n < 448)  v = fW[(n - 320) * (2 * DD) + DD + i];
        else if (n == 448) v = dfW[i];
        else               v = 0.f;
        g_WbigT[idx] = v;   // idx == i*NOUT + n, consecutive writes
    }
    for (int idx = gtid; idx < DD * DD; idx += gstr) {
        int i = idx >> 7, j = idx & 127;
        g_fWT[i * DD + j] = fW[j * (2 * DD) + i];
    }
    if (blockIdx.x == 0) {
        const int warp = threadIdx.x >> 5, lane = threadIdx.x & 31;
        float4 v0 = *(const float4*)&vemb[lane * 4];
        float4 v1 = *(const float4*)&vemb[DD + lane * 4];
        for (int d = warp; d < DD; d += 8) {
            float4 e4 = *(const float4*)&eW[d * DD + lane * 4];
            float4 a4 = *(const float4*)&aW[d * DD + lane * 4];
            float e0 = e4.x * v0.x + e4.y * v0.y + e4.z * v0.z + e4.w * v0.w;
            float e1 = e4.x * v1.x + e4.y * v1.y + e4.z * v1.z + e4.w * v1.w;
            float a0 = a4.x * v0.x + a4.y * v0.y + a4.z * v0.z + a4.w * v0.w;
            float a1 = a4.x * v1.x + a4.y * v1.y + a4.z * v1.z + a4.w * v1.w;
#pragma unroll
            for (int off = 16; off; off >>= 1) {
                e0 += __shfl_xor_sync(0xffffffffu, e0, off);
                e1 += __shfl_xor_sync(0xffffffffu, e1, off);
                a0 += __shfl_xor_sync(0xffffffffu, a0, off);
                a1 += __shfl_xor_sync(0xffffffffu, a1, off);
            }
            if (lane == 0) {
                float ebd = eb[d], abd = ab[d];
                g_ebias[d] = e0 + ebd;  g_ebias[DD + d] = e1 + ebd;
                g_abias[d] = a0 + abd;  g_abias[DD + d] = a1 + abd;
            }
        }
    }
}

// ---------------------------------------------------------------------------
// K0t: transpose k_emb [NC,DD] -> g_kembT [DD,KT] (pad cols stay 0-init)
// ---------------------------------------------------------------------------
__global__ void k0_transpose(const float* __restrict__ kemb) {
    __shared__ float t[32][33];
    const int bx = blockIdx.x * 32, by = blockIdx.y * 32;
    const int x = threadIdx.x, y = threadIdx.y;
#pragma unroll
    for (int i = 0; i < 32; i += 8) {
        int c = bx + y + i;
        t[y + i][x] = (c < NC) ? kemb[c * DD + by + x] : 0.f;
    }
    __syncthreads();
#pragma unroll
    for (int i = 0; i < 32; i += 8)
        g_kembT[(by + y + i) * KT + bx + x] = t[x][y + i];
}

// ---------------------------------------------------------------------------
// K1: Z = k_emb @ Wbig^T  (10112 x 512 x 128). Tile 128(c) x 64(n), BK=32,
// 256 threads, 8x4 microtile, cp.async double-buffered. 632 blocks @ 2/SM.
// ---------------------------------------------------------------------------
__global__ void __launch_bounds__(256, 2) k1_gemm() {
    __shared__ __align__(16) float As[2][32 * 128];   // 32 KB
    __shared__ __align__(16) float Bs[2][32 * 64];    // 16 KB
    const int cb = blockIdx.x * 128;
    const int nb = blockIdx.y * 64;
    const int tid = threadIdx.x;
    const int tx = tid & 15, ty = tid >> 4;
    const int m0 = ty * 8, n0 = tx * 4;

    float acc[8][4];
#pragma unroll
    for (int i = 0; i < 8; i++)
#pragma unroll
        for (int j = 0; j < 4; j++) acc[i][j] = 0.f;

    auto issue = [&](int buf, int ko) {
#pragma unroll
        for (int i = 0; i < 4; i++) {
            int f = tid + i * 256;               // 0..1023 float4 slots (A)
            int k = f >> 5, c4 = (f & 31) * 4;
            cp16(smem_u32(&As[buf][k * 128 + c4]),
                 &g_kembT[(ko + k) * KT + cb + c4]);
        }
#pragma unroll
        for (int i = 0; i < 2; i++) {
            int f = tid + i * 256;               // 0..511 float4 slots (B)
            int k = f >> 4, c4 = (f & 15) * 4;
            cp16(smem_u32(&Bs[buf][k * 64 + c4]),
                 &g_WbigT[(ko + k) * NOUT + nb + c4]);
        }
        asm volatile("cp.async.commit_group;" ::: "memory");
    };

    issue(0, 0);
    for (int it = 0; it < 4; it++) {
        asm volatile("cp.async.wait_group 0;" ::: "memory");
        __syncthreads();
        if (it < 3) issue((it + 1) & 1, (it + 1) * 32);
        const float* Ab = &As[it & 1][0];
        const float* Bb = &Bs[it & 1][0];
#pragma unroll
        for (int k = 0; k < 32; k++) {
            float a[8], b[4];
            *(float4*)&a[0] = *(const float4*)&Ab[k * 128 + m0];
            *(float4*)&a[4] = *(const float4*)&Ab[k * 128 + m0 + 4];
            *(float4*)&b[0] = *(const float4*)&Bb[k * 64 + n0];
#pragma unroll
            for (int i = 0; i < 8; i++)
#pragma unroll
                for (int j = 0; j < 4; j++)
                    acc[i][j] = fmaf(a[i], b[j], acc[i][j]);
        }
        __syncthreads();
    }
#pragma unroll
    for (int i = 0; i < 8; i++) {
        int c = cb + m0 + i;
        if (c < NC)
            *(float4*)&g_Z[c * NOUT + nb + n0] = *(float4*)&acc[i][0];
    }
}

// ---------------------------------------------------------------------------
// K_ea: fused per-token softmax (w -> g_Wg, [b][g][t][m] layout) + gates.
// Block = 8 tokens, 256 threads. Phase 1: warp per token softmax over 64.
// Phase 2: gates, 2 tokens per pass. No smem, no barriers.
// ---------------------------------------------------------------------------
__global__ void __launch_bounds__(256) k_ea(const int* __restrict__ q,
                                            const int* __restrict__ r) {
    const int tid = threadIdx.x;
    const int tok0 = blockIdx.x * 8;
    {   // softmax: warp w -> token tok0+w
        const int warp = tid >> 5, lane = tid & 31;
        const int tok = tok0 + warp;
        const int c = q[tok];
        const float* z = &g_Z[c * NOUT];
        float x0 = z[lane], x1 = z[lane + 32];
        float mx = fmaxf(x0, x1);
#pragma unroll
        for (int off = 16; off; off >>= 1)
            mx = fmaxf(mx, __shfl_xor_sync(0xffffffffu, mx, off));
        float e0 = __expf(x0 - mx), e1 = __expf(x1 - mx);
        float s = e0 + e1;
#pragma unroll
        for (int off = 16; off; off >>= 1)
            s += __shfl_xor_sync(0xffffffffu, s, off);
        float inv = __fdividef(1.f, s);
        const int b = tok / LL, t = tok - b * LL;
        const int g0 = lane >> 4, mi = lane & 15;
        g_Wg[((b * GG + g0)     * LL + t) * MG + mi] = e0 * inv;
        g_Wg[((b * GG + g0 + 2) * LL + t) * MG + mi] = e1 * inv;
    }
    {   // gates
        const int d = tid & 127;
        const int half = tid >> 7;
        const float eb0 = g_ebias[d], eb1 = g_ebias[DD + d];
        const float ab0 = g_abias[d], ab1 = g_abias[DD + d];
#pragma unroll
        for (int tt = 0; tt < 4; tt++) {
            const int tok = tok0 + tt * 2 + half;
            const int c = q[tok];
            const int rr = r[tok];
            float e = fsigmoid(g_Z[c * NOUT + 64 + d]  + (rr ? eb1 : eb0));
            float a = ftanh  (g_Z[c * NOUT + 192 + d] + (rr ? ab1 : ab0));
            g_E[tok * DD + d] = e;
            g_A[tok * DD + d] = a;
        }
    }
}

// ---------------------------------------------------------------------------
// K3: sequential scan. Block = (b, m-group). Thread d owns column d, MG=16
// state rows in registers. w table streamed contiguously into smem; E/A
// prefetched 2 steps ahead. Zero barriers / MUFU in the main loop.
// ---------------------------------------------------------------------------
__global__ void __launch_bounds__(128) k3_scan(const float* __restrict__ Mv0) {
    __shared__ float wtab[LL * MG];   // 12.8 KB
    const int b = blockIdx.x >> 2;
    const int g = blockIdx.x & 3;
    const int d = threadIdx.x;

    {   // contiguous 12.8 KB stream
        const float4* src = (const float4*)&g_Wg[(b * GG + g) * LL * MG];
        float4* dst = (float4*)wtab;
#pragma unroll
        for (int i = 0; i < 7; i++) {
            int idx = d + i * 128;
            if (idx < LL * MG / 4) dst[idx] = src[idx];
        }
    }
    float Mv[MG];
#pragma unroll
    for (int j = 0; j < MG; j++) Mv[j] = Mv0[(g * MG + j) * DD + d];
    __syncthreads();

    const float* Ep = &g_E[b * LL * DD + d];
    const float* Ap = &g_A[b * LL * DD + d];
    float ee0 = Ep[0],  aa0 = Ap[0];
    float ee1 = Ep[DD], aa1 = Ap[DD];
    float* outp = &g_preads[(b * LL * GG + g) * DD + d];

#pragma unroll 2
    for (int t = 0; t < LL; t++) {
        const int tp = (t < LL - 2) ? t + 2 : LL - 1;
        float ee2 = Ep[tp * DD];
        float aa2 = Ap[tp * DD];

        float r0 = 0.f, r1 = 0.f;
        const float* wp = &wtab[t * MG];
#pragma unroll
        for (int j = 0; j < MG; j += 2) {
            float w0 = wp[j], w1 = wp[j + 1];
            r0 = fmaf(w0, Mv[j], r0);
            r1 = fmaf(w1, Mv[j + 1], r1);
            Mv[j]     = fmaf(w0, fmaf(-ee0, Mv[j],     aa0), Mv[j]);
            Mv[j + 1] = fmaf(w1, fmaf(-ee0, Mv[j + 1], aa0), Mv[j + 1]);
        }
        outp[t * (GG * DD)] = r0 + r1;
        ee0 = ee1; aa0 = aa1;
        ee1 = ee2; aa1 = aa2;
    }
}

// ---------------------------------------------------------------------------
// K4: tiled GEMM epilogue, 64(tok) x 128(j) tiles, 400 blocks @ 3/SM.
//   f = tanh(reads @ fWr^T + fk(c) + f_b); p = sigmoid(3*tanh(f.abW+ab_b)-qd)
// ---------------------------------------------------------------------------
__global__ void __launch_bounds__(256, 3) k4_final(const int* __restrict__ q,
                                                   const float* __restrict__ f_b,
                                                   const float* __restrict__ abW,
                                                   const float* __restrict__ ab_b,
                                                   const float* __restrict__ df_b,
                                                   float* __restrict__ out) {
    __shared__ __align__(16) float As[32 * 64];    // 8 KB
    __shared__ __align__(16) float Bs[32 * 128];   // 16 KB
    const int tok0 = blockIdx.x * 64;
    const int tid = threadIdx.x;
    const int tx = tid & 15, ty = tid >> 4;
    const int m0 = ty * 4, n0 = tx * 8;

    float acc[4][8];
#pragma unroll
    for (int i = 0; i < 4; i++)
#pragma unroll
        for (int j = 0; j < 8; j++) acc[i][j] = 0.f;

    float abw[8], fb[8];
#pragma unroll
    for (int j = 0; j < 8; j++) {
        abw[j] = abW[n0 + j];
        fb[j]  = f_b[n0 + j];
    }
    const float abb = ab_b[0];
    const float dfb = df_b[0];

    for (int ko = 0; ko < DD; ko += 32) {
        // B chunk via cp.async (g_fWT rows are [k][j])
#pragma unroll
        for (int i = 0; i < 4; i++) {
            int f = tid + i * 256;
            int k = f >> 5, c4 = (f & 31) * 4;
            cp16(smem_u32(&Bs[k * 128 + c4]), &g_fWT[(ko + k) * DD + c4]);
        }
        asm volatile("cp.async.commit_group;" ::: "memory");
        // A chunk: sum 4 group partials, store transposed [k][token]
#pragma unroll
        for (int i = 0; i < 2; i++) {
            int slot = tid + i * 256;            // 0..511 float4 slots
            int tok = slot >> 3, i4 = slot & 7;
            const float* p = &g_preads[(tok0 + tok) * (GG * DD) + ko + i4 * 4];
            float4 v0 = *(const float4*)&p[0];
            float4 v1 = *(const float4*)&p[DD];
            float4 v2 = *(const float4*)&p[2 * DD];
            float4 v3 = *(const float4*)&p[3 * DD];
            As[(i4 * 4 + 0) * 64 + tok] = v0.x + v1.x + v2.x + v3.x;
            As[(i4 * 4 + 1) * 64 + tok] = v0.y + v1.y + v2.y + v3.y;
            As[(i4 * 4 + 2) * 64 + tok] = v0.z + v1.z + v2.z + v3.z;
            As[(i4 * 4 + 3) * 64 + tok] = v0.w + v1.w + v2.w + v3.w;
        }
        asm volatile("cp.async.wait_group 0;" ::: "memory");
        __syncthreads();
#pragma unroll
        for (int k = 0; k < 32; k++) {
            float a[4], b[8];
            *(float4*)&a[0] = *(const float4*)&As[k * 64 + m0];
            *(float4*)&b[0] = *(const float4*)&Bs[k * 128 + n0];
            *(float4*)&b[4] = *(const float4*)&Bs[k * 128 + n0 + 4];
#pragma unroll
            for (int i = 0; i < 4; i++)
#pragma unroll
                for (int j = 0; j < 8; j++)
                    acc[i][j] = fmaf(a[i], b[j], acc[i][j]);
        }
        __syncthreads();
    }

    // Epilogue: per token row, tanh + dot with abW, reduce across tx (16)
#pragma unroll
    for (int i = 0; i < 4; i++) {
        const int tok = tok0 + m0 + i;
        const int c = q[tok];                  // uniform over the 16 tx lanes
        float part = 0.f;
#pragma unroll
        for (int j = 0; j < 8; j++) {
            float fk = g_Z[c * NOUT + 320 + n0 + j] + fb[j];
            part = fmaf(ftanh(acc[i][j] + fk), abw[j], part);
        }
        part += __shfl_down_sync(0xffffffffu, part, 8, 16);
        part += __shfl_down_sync(0xffffffffu, part, 4, 16);
        part += __shfl_down_sync(0xffffffffu, part, 2, 16);
        part += __shfl_down_sync(0xffffffffu, part, 1, 16);
        if (tx == 0) {
            float stu = ftanh(part + abb);
            float qd = ftanh(g_Z[c * NOUT + 448] + dfb);
            out[tok] = fsigmoid(3.f * stu - qd);
        }
    }
}

// ---------------------------------------------------------------------------
extern "C" void kernel_launch(void* const* d_in, const int* in_sizes, int n_in,
                              void* d_out, int out_size) {
    const int*   q     = (const int*)d_in[0];
    const int*   r     = (const int*)d_in[1];
    const float* k_emb = (const float*)d_in[2];
    const float* v_emb = (const float*)d_in[3];
    const float* Mk    = (const float*)d_in[4];
    const float* Mv0   = (const float*)d_in[5];
    const float* f_W   = (const float*)d_in[6];
    const float* f_b   = (const float*)d_in[7];
    const float* e_W   = (const float*)d_in[8];
    const float* e_b   = (const float*)d_in[9];
    const float* a_W   = (const float*)d_in[10];
    const float* a_b   = (const float*)d_in[11];
    const float* ab_W  = (const float*)d_in[12];
    const float* ab_b  = (const float*)d_in[13];
    const float* df_W  = (const float*)d_in[14];
    const float* df_b  = (const float*)d_in[15];
    float* out = (float*)d_out;

    k0_prep<<<64, 256>>>(Mk, e_W, a_W, f_W, df_W, v_emb, e_b, a_b);
    dim3 gt((NC + 31) / 32, DD / 32);
    k0_transpose<<<gt, dim3(32, 8)>>>(k_emb);
    dim3 g1(KT / 128, NOUT / 64);
    k1_gemm<<<g1, 256>>>();
    k_ea<<<NTOK / 8, 256>>>(q, r);
    k3_scan<<<BB * GG, 128>>>(Mv0);
    k4_final<<<NTOK / 64, 256>>>(q, f_b, ab_W, ab_b, df_b, out);
}